// round 7
// baseline (speedup 1.0000x reference)
#include <cuda_runtime.h>
#include <cuda_fp16.h>
#include <math.h>
#include <stdint.h>

#define NTOK   4096
#define DIM    1024
#define NEXP   8
#define HIDDEN 4096

#define BM 128
#define BN 128
#define BKH 64            // K halfs per SMEM k-tile
#define NT 128
#define ROWB 144          // SMEM row stride bytes (128 payload + 16 pad)

// ---------------- scratch (__device__ statics — alloc-free) ----------------
__device__ int    g_cnt[NEXP];
__device__ int    g_list[NEXP][NTOK];
__device__ float  g_gw[NEXP][NTOK];
__device__ __half g_xh[(size_t)NTOK * DIM];
__device__ __half g_h[(size_t)NTOK * 2 * HIDDEN];
__device__ float  g_part[(size_t)NTOK * 2 * DIM];
__device__ __half g_W1t[(size_t)NEXP * HIDDEN * DIM];     // [e][n][k]
__device__ __half g_W2t[(size_t)NEXP * DIM * HIDDEN];

// ---------------- helpers ----------------
__device__ __forceinline__ uint32_t smem_u32(const void* p) {
    uint32_t a;
    asm("{ .reg .u64 t; cvta.to.shared.u64 t, %1; cvt.u32.u64 %0, t; }" : "=r"(a) : "l"(p));
    return a;
}
__device__ __forceinline__ void cp_async16(uint32_t dst, const void* src) {
    asm volatile("cp.async.cg.shared.global [%0], [%1], 16;" :: "r"(dst), "l"(src));
}
#define CP_COMMIT() asm volatile("cp.async.commit_group;" ::: "memory")
#define CP_WAIT1()  asm volatile("cp.async.wait_group 1;" ::: "memory")

__device__ __forceinline__ void ldsm_x4(uint32_t* r, uint32_t addr) {
    asm volatile("ldmatrix.sync.aligned.m8n8.x4.shared.b16 {%0,%1,%2,%3}, [%4];"
                 : "=r"(r[0]), "=r"(r[1]), "=r"(r[2]), "=r"(r[3]) : "r"(addr));
}
// f16-accumulator HMMA (in-out d)
__device__ __forceinline__ void mma_f16h(uint32_t& d0, uint32_t& d1,
                                         const uint32_t* a, uint32_t b0, uint32_t b1) {
    asm volatile(
        "mma.sync.aligned.m16n8k16.row.col.f16.f16.f16.f16 "
        "{%0,%1}, {%2,%3,%4,%5}, {%6,%7}, {%0,%1};"
        : "+r"(d0), "+r"(d1)
        : "r"(a[0]), "r"(a[1]), "r"(a[2]), "r"(a[3]), "r"(b0), "r"(b1));
}

// ---------------- kernel 0: reset counters ----------------
__global__ void zero_cnt_kernel() {
    if (threadIdx.x < NEXP) g_cnt[threadIdx.x] = 0;
}

// ---------------- kernel 1: gating (1 warp per token) ----------------
__global__ void gate_kernel(const float* __restrict__ x,
                            const float* __restrict__ Wg,
                            const float* __restrict__ bg) {
    int warp = blockIdx.x * (blockDim.x >> 5) + (threadIdx.x >> 5);
    int lane = threadIdx.x & 31;
    if (warp >= NTOK) return;

    const float* xr = x + (size_t)warp * DIM;
    float acc[NEXP];
#pragma unroll
    for (int e = 0; e < NEXP; e++) acc[e] = 0.f;
    for (int d = lane; d < DIM; d += 32) {
        float xv = xr[d];
        const float4* w = reinterpret_cast<const float4*>(Wg + (size_t)d * NEXP);
        float4 w0 = w[0], w1 = w[1];
        acc[0] = fmaf(xv, w0.x, acc[0]); acc[1] = fmaf(xv, w0.y, acc[1]);
        acc[2] = fmaf(xv, w0.z, acc[2]); acc[3] = fmaf(xv, w0.w, acc[3]);
        acc[4] = fmaf(xv, w1.x, acc[4]); acc[5] = fmaf(xv, w1.y, acc[5]);
        acc[6] = fmaf(xv, w1.z, acc[6]); acc[7] = fmaf(xv, w1.w, acc[7]);
    }
#pragma unroll
    for (int off = 16; off > 0; off >>= 1)
#pragma unroll
        for (int e = 0; e < NEXP; e++)
            acc[e] += __shfl_xor_sync(0xffffffffu, acc[e], off);

    if (lane == 0) {
        float lg[NEXP], mx = -1e30f;
#pragma unroll
        for (int e = 0; e < NEXP; e++) { lg[e] = acc[e] + bg[e]; mx = fmaxf(mx, lg[e]); }
        float p[NEXP], s = 0.f;
#pragma unroll
        for (int e = 0; e < NEXP; e++) { p[e] = expf(lg[e] - mx); s += p[e]; }
        float inv = 1.f / s;
        int i0 = 0;
#pragma unroll
        for (int e = 1; e < NEXP; e++) if (p[e] > p[i0]) i0 = e;
        int i1 = (i0 == 0) ? 1 : 0;
#pragma unroll
        for (int e = 0; e < NEXP; e++) if (e != i0 && p[e] > p[i1]) i1 = e;

        int pos0 = atomicAdd(&g_cnt[i0], 1);
        g_list[i0][pos0] = warp * 2 + 0;  g_gw[i0][pos0] = p[i0] * inv;
        int pos1 = atomicAdd(&g_cnt[i1], 1);
        g_list[i1][pos1] = warp * 2 + 1;  g_gw[i1][pos1] = p[i1] * inv;
    }
}

// ---------------- x fp16 pre-round ----------------
__global__ void round_x_kernel(const float* __restrict__ x) {
    int i = blockIdx.x * blockDim.x + threadIdx.x;
    if (i >= NTOK * DIM / 4) return;
    float4 v = ((const float4*)x)[i];
    __half2* o = (__half2*)(g_xh + (size_t)i * 4);
    o[0] = __floats2half2_rn(v.x, v.y);
    o[1] = __floats2half2_rn(v.z, v.w);
}

// ------------- weight transpose + fp16 cvt: in fp32 [e][K][N] -> half [e][N][K] -------
// 64k x 32n tile; coalesced 128B reads, half2 writes. Row stride 66 floats keeps
// the float2 shared loads 8B-aligned (65 was the R6 misalignment bug).
__global__ void transpose_cvt_kernel(const float* __restrict__ in, __half* __restrict__ out,
                                     int K, int N) {
    __shared__ float tile[32][66];
    int e = blockIdx.z;
    size_t base = (size_t)e * K * N;
    int n0 = blockIdx.x * 32, k0 = blockIdx.y * 64;
    int tn = threadIdx.x & 31;
    int tk = threadIdx.x >> 5;          // 0..7
#pragma unroll
    for (int i = 0; i < 8; i++) {
        int k = tk + i * 8;
        tile[tn][k] = in[base + (size_t)(k0 + k) * N + n0 + tn];
    }
    __syncthreads();
    int w = threadIdx.x >> 5, lane = threadIdx.x & 31;
#pragma unroll
    for (int r = 0; r < 4; r++) {
        int n = w + r * 8;
        float2 v = *(const float2*)&tile[n][2 * lane];
        *(__half2*)(out + base + (size_t)(n0 + n) * K + k0 + 2 * lane) =
            __floats2half2_rn(v.x, v.y);
    }
}

// ---------------- fp16 mma expert GEMM: f16-accum chunks drained to fp32 ----------------
// MODE 0: A = gathered g_xh rows, B = W1t, epi: half(relu(acc+b1)) -> g_h
// MODE 1: A = gathered g_h rows,  B = W2t, epi: gw*(acc+b2)        -> g_part
template<int MODE, int KDIM, int NCOLS>
__global__ void __launch_bounds__(NT, 2)
moe_mma(const __half* __restrict__ Asrc, const __half* __restrict__ Wt,
        const float* __restrict__ bias) {
    const int e   = blockIdx.z;
    const int cnt = g_cnt[e];
    const int m0  = blockIdx.x * BM;
    if (m0 >= cnt) return;

    extern __shared__ char smem[];
    int*   s_row = (int*)smem;                 // [128]
    float* s_gw  = (float*)(smem + 512);       // [128]
    const int TILE_B  = BM * ROWB;             // 18432 B
    const int STAGE_B = 2 * TILE_B;

    const int tid  = threadIdx.x;
    const int wid  = tid >> 5, lane = tid & 31;
    const int wm   = (wid >> 1) * 64;
    const int wn   = (wid & 1) * 64;
    const int g    = lane >> 2;
    const int tg   = lane & 3;

    for (int i = tid; i < BM; i += NT) {
        int r = m0 + i;
        if (r < cnt) { s_row[i] = g_list[e][r]; s_gw[i] = g_gw[e][r]; }
        else         { s_row[i] = -1;           s_gw[i] = 0.f; }
    }
    __syncthreads();

    const int gn0 = blockIdx.y * BN;
    const uint32_t tiles_b = smem_u32(smem) + 1024;

    const int lrow = tid >> 3, c8 = tid & 7;
    uint32_t a_off[8];
#pragma unroll
    for (int i = 0; i < 8; i++) {
        int p = s_row[lrow + i * 16];
        int arow = (p >= 0) ? (MODE == 0 ? (p >> 1) : p) : 0;
        a_off[i] = (uint32_t)arow * KDIM + c8 * 8;
    }
    const __half* b_base = Wt + ((size_t)e * NCOLS + gn0 + lrow) * KDIM + c8 * 8;
    const uint32_t a_dst0 = (uint32_t)(lrow * ROWB + c8 * 16);
    const uint32_t b_dst0 = (uint32_t)(TILE_B + lrow * ROWB + c8 * 16);
    const uint32_t rstep  = 16 * ROWB;

    const uint32_t a_lane = (uint32_t)((lane & 15) * ROWB + (lane >> 4) * 16);
    const int nloc  = (lane & 7) + ((lane >> 4) << 3);
    const uint32_t b_lane = (uint32_t)(nloc * ROWB + ((lane >> 3) & 1) * 16);

    float acc[4][8][4];
#pragma unroll
    for (int i = 0; i < 4; i++)
#pragma unroll
        for (int j = 0; j < 8; j++)
#pragma unroll
            for (int q = 0; q < 4; q++) acc[i][j][q] = 0.f;

    const int KT = KDIM / BKH;

#pragma unroll
    for (int i = 0; i < 8; i++) {
        cp_async16(tiles_b + a_dst0 + i * rstep, Asrc + a_off[i]);
        cp_async16(tiles_b + b_dst0 + i * rstep, b_base + (size_t)i * 16 * KDIM);
    }
    CP_COMMIT();

#pragma unroll 1
    for (int t = 0; t < KT; ++t) {
        if (t + 1 < KT) {
            const uint32_t sb = tiles_b + ((t + 1) & 1) * STAGE_B;
            const int k1 = (t + 1) * BKH;
#pragma unroll
            for (int i = 0; i < 8; i++) {
                cp_async16(sb + a_dst0 + i * rstep, Asrc + a_off[i] + k1);
                cp_async16(sb + b_dst0 + i * rstep, b_base + (size_t)i * 16 * KDIM + k1);
            }
        }
        CP_COMMIT();
        CP_WAIT1();
        __syncthreads();

        const uint32_t As_b = tiles_b + (t & 1) * STAGE_B;
        const uint32_t Bs_b = As_b + TILE_B;
        // two chunk-pairs per 64-half k-tile: (k16 steps 0,1) and (2,3)
#pragma unroll
        for (int sp = 0; sp < 2; sp++) {
            uint32_t af[4][2][4];
#pragma unroll
            for (int i = 0; i < 4; i++) {
                ldsm_x4(af[i][0], As_b + (uint32_t)(wm + 16 * i) * ROWB + (2 * sp) * 32 + a_lane);
                ldsm_x4(af[i][1], As_b + (uint32_t)(wm + 16 * i) * ROWB + (2 * sp + 1) * 32 + a_lane);
            }
#pragma unroll
            for (int j2 = 0; j2 < 4; j2++) {
                uint32_t bf0[4], bf1[4];
                ldsm_x4(bf0, Bs_b + (uint32_t)(wn + 16 * j2) * ROWB + (2 * sp) * 32 + b_lane);
                ldsm_x4(bf1, Bs_b + (uint32_t)(wn + 16 * j2) * ROWB + (2 * sp + 1) * 32 + b_lane);
#pragma unroll
                for (int i = 0; i < 4; i++)
#pragma unroll
                    for (int tt = 0; tt < 2; tt++) {
                        uint32_t d0 = 0, d1 = 0;
                        mma_f16h(d0, d1, af[i][0], bf0[2 * tt], bf0[2 * tt + 1]);
                        mma_f16h(d0, d1, af[i][1], bf1[2 * tt], bf1[2 * tt + 1]);
                        float2 f0 = __half22float2(*reinterpret_cast<__half2*>(&d0));
                        float2 f1 = __half22float2(*reinterpret_cast<__half2*>(&d1));
                        float* ac = acc[i][2 * j2 + tt];
                        ac[0] += f0.x; ac[1] += f0.y; ac[2] += f1.x; ac[3] += f1.y;
                    }
            }
        }
        __syncthreads();
    }

    // ---------------- epilogue ----------------
#pragma unroll
    for (int i = 0; i < 4; i++) {
        const int rl = wm + i * 16 + g;
        const int pl = s_row[rl],  ph = s_row[rl + 8];
        const float gl = s_gw[rl], gh2 = s_gw[rl + 8];
#pragma unroll
        for (int j = 0; j < 8; j++) {
            const int n = gn0 + wn + j * 8 + 2 * tg;
            const float2 bb = *(const float2*)(bias + (size_t)e * NCOLS + n);
            if (MODE == 0) {
                if (pl >= 0)
                    *(__half2*)(g_h + (size_t)pl * HIDDEN + n) =
                        __floats2half2_rn(fmaxf(acc[i][j][0] + bb.x, 0.f),
                                          fmaxf(acc[i][j][1] + bb.y, 0.f));
                if (ph >= 0)
                    *(__half2*)(g_h + (size_t)ph * HIDDEN + n) =
                        __floats2half2_rn(fmaxf(acc[i][j][2] + bb.x, 0.f),
                                          fmaxf(acc[i][j][3] + bb.y, 0.f));
            } else {
                if (pl >= 0) {
                    float2 v;
                    v.x = gl * (acc[i][j][0] + bb.x);
                    v.y = gl * (acc[i][j][1] + bb.y);
                    *(float2*)(g_part + (size_t)pl * DIM + n) = v;
                }
                if (ph >= 0) {
                    float2 v;
                    v.x = gh2 * (acc[i][j][2] + bb.x);
                    v.y = gh2 * (acc[i][j][3] + bb.y);
                    *(float2*)(g_part + (size_t)ph * DIM + n) = v;
                }
            }
        }
    }
}

// ---------------- kernel: combine the two slots per token ----------------
__global__ void combine_kernel(float* __restrict__ out) {
    int i = blockIdx.x * blockDim.x + threadIdx.x;
    const int total = NTOK * DIM / 4;
    if (i >= total) return;
    int n = i / (DIM / 4), d4 = i % (DIM / 4);
    const float4 a = *((const float4*)(g_part + (size_t)(2 * n)     * DIM) + d4);
    const float4 b = *((const float4*)(g_part + (size_t)(2 * n + 1) * DIM) + d4);
    float4 r; r.x = a.x + b.x; r.y = a.y + b.y; r.z = a.z + b.z; r.w = a.w + b.w;
    ((float4*)out)[i] = r;
}

// ---------------- launch ----------------
static constexpr int SMEM_BYTES = 1024 + 2 * 2 * BM * ROWB;   // 74752

extern "C" void kernel_launch(void* const* d_in, const int* in_sizes, int n_in,
                              void* d_out, int out_size) {
    const float* x  = (const float*)d_in[0];
    const float* Wg = (const float*)d_in[1];
    const float* bg = (const float*)d_in[2];
    const float* W1 = (const float*)d_in[3];
    const float* b1 = (const float*)d_in[4];
    const float* W2 = (const float*)d_in[5];
    const float* b2 = (const float*)d_in[6];
    float* out = (float*)d_out;

    cudaFuncSetAttribute(moe_mma<0, DIM, HIDDEN>,
                         cudaFuncAttributeMaxDynamicSharedMemorySize, SMEM_BYTES);
    cudaFuncSetAttribute(moe_mma<1, HIDDEN, DIM>,
                         cudaFuncAttributeMaxDynamicSharedMemorySize, SMEM_BYTES);

    __half* W1t; cudaGetSymbolAddress((void**)&W1t, g_W1t);
    __half* W2t; cudaGetSymbolAddress((void**)&W2t, g_W2t);
    __half* xh;  cudaGetSymbolAddress((void**)&xh,  g_xh);
    __half* gh;  cudaGetSymbolAddress((void**)&gh,  g_h);

    zero_cnt_kernel<<<1, 32>>>();
    gate_kernel<<<NTOK / 8, 256>>>(x, Wg, bg);
    round_x_kernel<<<(NTOK * DIM / 4 + 255) / 256, 256>>>(x);
    transpose_cvt_kernel<<<dim3(HIDDEN / 32, DIM / 64, NEXP), 256>>>(W1, W1t, DIM, HIDDEN);
    transpose_cvt_kernel<<<dim3(DIM / 32, HIDDEN / 64, NEXP), 256>>>(W2, W2t, HIDDEN, DIM);
    moe_mma<0, DIM, HIDDEN><<<dim3(NTOK / BM, HIDDEN / BN, NEXP), NT, SMEM_BYTES>>>(xh, W1t, b1);
    moe_mma<1, HIDDEN, DIM><<<dim3(NTOK / BM, DIM / BN, NEXP), NT, SMEM_BYTES>>>(gh, W2t, b2);
    combine_kernel<<<(NTOK * DIM / 4 + 255) / 256, 256>>>(out);
}

// round 8
// speedup vs baseline: 1.1065x; 1.1065x over previous
#include <cuda_runtime.h>
#include <cuda_fp16.h>
#include <math.h>
#include <stdint.h>

#define NTOK   4096
#define DIM    1024
#define NEXP   8
#define HIDDEN 4096

#define BM 128
#define BN 128
#define BKH 64            // K halfs per SMEM k-tile
#define NT 128
#define ROWB 144          // SMEM row stride bytes (128 payload + 16 pad)

// ---------------- scratch (__device__ statics — alloc-free) ----------------
__device__ int    g_cnt[NEXP];
__device__ int    g_list[NEXP][NTOK];
__device__ float  g_gw[NEXP][NTOK];
__device__ __half g_xh[(size_t)NTOK * DIM];
__device__ __half g_h[(size_t)NTOK * 2 * HIDDEN];
__device__ __half g_W1t[(size_t)NEXP * HIDDEN * DIM];     // [e][n][k]
__device__ __half g_W2t[(size_t)NEXP * DIM * HIDDEN];

// ---------------- helpers ----------------
__device__ __forceinline__ uint32_t smem_u32(const void* p) {
    uint32_t a;
    asm("{ .reg .u64 t; cvta.to.shared.u64 t, %1; cvt.u32.u64 %0, t; }" : "=r"(a) : "l"(p));
    return a;
}
__device__ __forceinline__ void cp_async16(uint32_t dst, const void* src) {
    asm volatile("cp.async.cg.shared.global [%0], [%1], 16;" :: "r"(dst), "l"(src));
}
#define CP_COMMIT() asm volatile("cp.async.commit_group;" ::: "memory")
#define CP_WAIT1()  asm volatile("cp.async.wait_group 1;" ::: "memory")

__device__ __forceinline__ void ldsm_x4(uint32_t* r, uint32_t addr) {
    asm volatile("ldmatrix.sync.aligned.m8n8.x4.shared.b16 {%0,%1,%2,%3}, [%4];"
                 : "=r"(r[0]), "=r"(r[1]), "=r"(r[2]), "=r"(r[3]) : "r"(addr));
}
__device__ __forceinline__ void mma_f16(float* d, const uint32_t* a, uint32_t b0, uint32_t b1) {
    asm volatile(
        "mma.sync.aligned.m16n8k16.row.col.f32.f16.f16.f32 "
        "{%0,%1,%2,%3}, {%4,%5,%6,%7}, {%8,%9}, {%0,%1,%2,%3};"
        : "+f"(d[0]), "+f"(d[1]), "+f"(d[2]), "+f"(d[3])
        : "r"(a[0]), "r"(a[1]), "r"(a[2]), "r"(a[3]), "r"(b0), "r"(b1));
}

// ---------------- kernel 0: zero output + counters ----------------
__global__ void zero_kernel(float* __restrict__ out) {
    int i = blockIdx.x * blockDim.x + threadIdx.x;     // float4 units
    if (i < NTOK * DIM / 4)
        ((float4*)out)[i] = make_float4(0.f, 0.f, 0.f, 0.f);
    if (blockIdx.x == 0 && threadIdx.x < NEXP) g_cnt[threadIdx.x] = 0;
}

// ---------------- kernel 1: gating + x fp16 cvt (1 warp per token) ----------------
__global__ void gate_kernel(const float* __restrict__ x,
                            const float* __restrict__ Wg,
                            const float* __restrict__ bg) {
    int warp = blockIdx.x * (blockDim.x >> 5) + (threadIdx.x >> 5);
    int lane = threadIdx.x & 31;
    if (warp >= NTOK) return;

    const float4* xr4 = (const float4*)(x + (size_t)warp * DIM);
    __half2* xo = (__half2*)(g_xh + (size_t)warp * DIM);

    float acc[NEXP];
#pragma unroll
    for (int e = 0; e < NEXP; e++) acc[e] = 0.f;

#pragma unroll
    for (int it = 0; it < 8; it++) {
        int i4 = lane + it * 32;                 // float4 index within the row
        float4 xv = xr4[i4];
        // fused fp16 conversion of this token row
        xo[2 * i4]     = __floats2half2_rn(xv.x, xv.y);
        xo[2 * i4 + 1] = __floats2half2_rn(xv.z, xv.w);
        const float* xs = (const float*)&xv;
#pragma unroll
        for (int c = 0; c < 4; c++) {
            float v = xs[c];
            const float4* w = reinterpret_cast<const float4*>(Wg + (size_t)(i4 * 4 + c) * NEXP);
            float4 w0 = w[0], w1 = w[1];
            acc[0] = fmaf(v, w0.x, acc[0]); acc[1] = fmaf(v, w0.y, acc[1]);
            acc[2] = fmaf(v, w0.z, acc[2]); acc[3] = fmaf(v, w0.w, acc[3]);
            acc[4] = fmaf(v, w1.x, acc[4]); acc[5] = fmaf(v, w1.y, acc[5]);
            acc[6] = fmaf(v, w1.z, acc[6]); acc[7] = fmaf(v, w1.w, acc[7]);
        }
    }
#pragma unroll
    for (int off = 16; off > 0; off >>= 1)
#pragma unroll
        for (int e = 0; e < NEXP; e++)
            acc[e] += __shfl_xor_sync(0xffffffffu, acc[e], off);

    if (lane == 0) {
        float lg[NEXP], mx = -1e30f;
#pragma unroll
        for (int e = 0; e < NEXP; e++) { lg[e] = acc[e] + bg[e]; mx = fmaxf(mx, lg[e]); }
        float p[NEXP], s = 0.f;
#pragma unroll
        for (int e = 0; e < NEXP; e++) { p[e] = expf(lg[e] - mx); s += p[e]; }
        float inv = 1.f / s;
        int i0 = 0;
#pragma unroll
        for (int e = 1; e < NEXP; e++) if (p[e] > p[i0]) i0 = e;
        int i1 = (i0 == 0) ? 1 : 0;
#pragma unroll
        for (int e = 0; e < NEXP; e++) if (e != i0 && p[e] > p[i1]) i1 = e;

        int pos0 = atomicAdd(&g_cnt[i0], 1);
        g_list[i0][pos0] = warp * 2 + 0;  g_gw[i0][pos0] = p[i0] * inv;
        int pos1 = atomicAdd(&g_cnt[i1], 1);
        g_list[i1][pos1] = warp * 2 + 1;  g_gw[i1][pos1] = p[i1] * inv;
    }
}

// ------------- weight transpose + fp16 cvt: in fp32 [e][K][N] -> half [e][N][K] -------
__global__ void transpose_cvt_kernel(const float* __restrict__ in, __half* __restrict__ out,
                                     int K, int N) {
    __shared__ float tile[32][66];
    int e = blockIdx.z;
    size_t base = (size_t)e * K * N;
    int n0 = blockIdx.x * 32, k0 = blockIdx.y * 64;
    int tn = threadIdx.x & 31;
    int tk = threadIdx.x >> 5;          // 0..7
#pragma unroll
    for (int i = 0; i < 8; i++) {
        int k = tk + i * 8;
        tile[tn][k] = in[base + (size_t)(k0 + k) * N + n0 + tn];
    }
    __syncthreads();
    int w = threadIdx.x >> 5, lane = threadIdx.x & 31;
#pragma unroll
    for (int r = 0; r < 4; r++) {
        int n = w + r * 8;
        float2 v = *(const float2*)&tile[n][2 * lane];
        *(__half2*)(out + base + (size_t)(n0 + n) * K + k0 + 2 * lane) =
            __floats2half2_rn(v.x, v.y);
    }
}

// ---------------- fp16 mma.sync expert GEMM (4 warps, 64x64 warp tile) ----------------
// MODE 0: A = gathered g_xh rows, B = W1t, epi: half(relu(acc+b1)) -> g_h
// MODE 1: A = gathered g_h rows,  B = W2t, epi: atomicAdd(out, gw*(acc+b2))
template<int MODE, int KDIM, int NCOLS>
__global__ void __launch_bounds__(NT, 2)
moe_mma(const __half* __restrict__ Asrc, const __half* __restrict__ Wt,
        const float* __restrict__ bias, float* __restrict__ out) {
    const int e   = blockIdx.z;
    const int cnt = g_cnt[e];
    const int m0  = blockIdx.x * BM;
    if (m0 >= cnt) return;

    extern __shared__ char smem[];
    int*   s_row = (int*)smem;                 // [128]
    float* s_gw  = (float*)(smem + 512);       // [128]
    const int TILE_B  = BM * ROWB;             // 18432 B
    const int STAGE_B = 2 * TILE_B;

    const int tid  = threadIdx.x;
    const int wid  = tid >> 5, lane = tid & 31;
    const int wm   = (wid >> 1) * 64;
    const int wn   = (wid & 1) * 64;
    const int g    = lane >> 2;
    const int tg   = lane & 3;

    for (int i = tid; i < BM; i += NT) {
        int r = m0 + i;
        if (r < cnt) { s_row[i] = g_list[e][r]; s_gw[i] = g_gw[e][r]; }
        else         { s_row[i] = -1;           s_gw[i] = 0.f; }
    }
    __syncthreads();

    const int gn0 = blockIdx.y * BN;
    const uint32_t tiles_b = smem_u32(smem) + 1024;

    const int lrow = tid >> 3, c8 = tid & 7;
    uint32_t a_off[8];
#pragma unroll
    for (int i = 0; i < 8; i++) {
        int p = s_row[lrow + i * 16];
        int arow = (p >= 0) ? (MODE == 0 ? (p >> 1) : p) : 0;
        a_off[i] = (uint32_t)arow * KDIM + c8 * 8;
    }
    const __half* b_base = Wt + ((size_t)e * NCOLS + gn0 + lrow) * KDIM + c8 * 8;
    const uint32_t a_dst0 = (uint32_t)(lrow * ROWB + c8 * 16);
    const uint32_t b_dst0 = (uint32_t)(TILE_B + lrow * ROWB + c8 * 16);
    const uint32_t rstep  = 16 * ROWB;

    const uint32_t a_lane = (uint32_t)((lane & 15) * ROWB + (lane >> 4) * 16);
    const int nloc  = (lane & 7) + ((lane >> 4) << 3);
    const uint32_t b_lane = (uint32_t)(nloc * ROWB + ((lane >> 3) & 1) * 16);

    float acc[4][8][4];
#pragma unroll
    for (int i = 0; i < 4; i++)
#pragma unroll
        for (int j = 0; j < 8; j++)
#pragma unroll
            for (int q = 0; q < 4; q++) acc[i][j][q] = 0.f;

    const int KT = KDIM / BKH;

#pragma unroll
    for (int i = 0; i < 8; i++) {
        cp_async16(tiles_b + a_dst0 + i * rstep, Asrc + a_off[i]);
        cp_async16(tiles_b + b_dst0 + i * rstep, b_base + (size_t)i * 16 * KDIM);
    }
    CP_COMMIT();

#pragma unroll 1
    for (int t = 0; t < KT; ++t) {
        if (t + 1 < KT) {
            const uint32_t sb = tiles_b + ((t + 1) & 1) * STAGE_B;
            const int k1 = (t + 1) * BKH;
#pragma unroll
            for (int i = 0; i < 8; i++) {
                cp_async16(sb + a_dst0 + i * rstep, Asrc + a_off[i] + k1);
                cp_async16(sb + b_dst0 + i * rstep, b_base + (size_t)i * 16 * KDIM + k1);
            }
        }
        CP_COMMIT();
        CP_WAIT1();
        __syncthreads();

        const uint32_t As_b = tiles_b + (t & 1) * STAGE_B;
        const uint32_t Bs_b = As_b + TILE_B;
#pragma unroll
        for (int s = 0; s < 4; s++) {
            const uint32_t kb = s * 32;
            uint32_t af[4][4];
#pragma unroll
            for (int i = 0; i < 4; i++)
                ldsm_x4(af[i], As_b + (uint32_t)(wm + 16 * i) * ROWB + kb + a_lane);
            uint32_t bf[4][4];
#pragma unroll
            for (int j2 = 0; j2 < 4; j2++)
                ldsm_x4(bf[j2], Bs_b + (uint32_t)(wn + 16 * j2) * ROWB + kb + b_lane);
#pragma unroll
            for (int i = 0; i < 4; i++)
#pragma unroll
                for (int j2 = 0; j2 < 4; j2++) {
                    mma_f16(acc[i][2 * j2],     af[i], bf[j2][0], bf[j2][1]);
                    mma_f16(acc[i][2 * j2 + 1], af[i], bf[j2][2], bf[j2][3]);
                }
        }
        __syncthreads();
    }

    // ---------------- epilogue ----------------
#pragma unroll
    for (int i = 0; i < 4; i++) {
        const int rl = wm + i * 16 + g;
        const int pl = s_row[rl],  ph = s_row[rl + 8];
        const float gl = s_gw[rl], gh2 = s_gw[rl + 8];
#pragma unroll
        for (int j = 0; j < 8; j++) {
            const int n = gn0 + wn + j * 8 + 2 * tg;
            const float2 bb = *(const float2*)(bias + (size_t)e * NCOLS + n);
            if (MODE == 0) {
                if (pl >= 0)
                    *(__half2*)(g_h + (size_t)pl * HIDDEN + n) =
                        __floats2half2_rn(fmaxf(acc[i][j][0] + bb.x, 0.f),
                                          fmaxf(acc[i][j][1] + bb.y, 0.f));
                if (ph >= 0)
                    *(__half2*)(g_h + (size_t)ph * HIDDEN + n) =
                        __floats2half2_rn(fmaxf(acc[i][j][2] + bb.x, 0.f),
                                          fmaxf(acc[i][j][3] + bb.y, 0.f));
            } else {
                // direct scatter-add into out: each element gets exactly two
                // addends onto 0.0f — fp add is commutative, so bitwise
                // deterministic regardless of atomic ordering.
                if (pl >= 0) {
                    float* op = out + (size_t)(pl >> 1) * DIM + n;
                    atomicAdd(op,     gl * (acc[i][j][0] + bb.x));
                    atomicAdd(op + 1, gl * (acc[i][j][1] + bb.y));
                }
                if (ph >= 0) {
                    float* op = out + (size_t)(ph >> 1) * DIM + n;
                    atomicAdd(op,     gh2 * (acc[i][j][2] + bb.x));
                    atomicAdd(op + 1, gh2 * (acc[i][j][3] + bb.y));
                }
            }
        }
    }
}

// ---------------- launch ----------------
static constexpr int SMEM_BYTES = 1024 + 2 * 2 * BM * ROWB;   // 74752

extern "C" void kernel_launch(void* const* d_in, const int* in_sizes, int n_in,
                              void* d_out, int out_size) {
    const float* x  = (const float*)d_in[0];
    const float* Wg = (const float*)d_in[1];
    const float* bg = (const float*)d_in[2];
    const float* W1 = (const float*)d_in[3];
    const float* b1 = (const float*)d_in[4];
    const float* W2 = (const float*)d_in[5];
    const float* b2 = (const float*)d_in[6];
    float* out = (float*)d_out;

    cudaFuncSetAttribute(moe_mma<0, DIM, HIDDEN>,
                         cudaFuncAttributeMaxDynamicSharedMemorySize, SMEM_BYTES);
    cudaFuncSetAttribute(moe_mma<1, HIDDEN, DIM>,
                         cudaFuncAttributeMaxDynamicSharedMemorySize, SMEM_BYTES);

    __half* W1t; cudaGetSymbolAddress((void**)&W1t, g_W1t);
    __half* W2t; cudaGetSymbolAddress((void**)&W2t, g_W2t);
    __half* xh;  cudaGetSymbolAddress((void**)&xh,  g_xh);
    __half* gh;  cudaGetSymbolAddress((void**)&gh,  g_h);

    zero_kernel<<<(NTOK * DIM / 4 + 255) / 256, 256>>>(out);
    gate_kernel<<<NTOK / 8, 256>>>(x, Wg, bg);
    transpose_cvt_kernel<<<dim3(HIDDEN / 32, DIM / 64, NEXP), 256>>>(W1, W1t, DIM, HIDDEN);
    transpose_cvt_kernel<<<dim3(DIM / 32, HIDDEN / 64, NEXP), 256>>>(W2, W2t, HIDDEN, DIM);
    moe_mma<0, DIM, HIDDEN><<<dim3(NTOK / BM, HIDDEN / BN, NEXP), NT, SMEM_BYTES>>>(xh, W1t, b1, nullptr);
    moe_mma<1, HIDDEN, DIM><<<dim3(NTOK / BM, DIM / BN, NEXP), NT, SMEM_BYTES>>>(gh, W2t, b2, out);
}

// round 9
// speedup vs baseline: 1.1136x; 1.0064x over previous
#include <cuda_runtime.h>
#include <cuda_fp16.h>
#include <math.h>
#include <stdint.h>

#define NTOK   4096
#define DIM    1024
#define NEXP   8
#define HIDDEN 4096

#define BM 128
#define BN 128
#define BKH 64            // K halfs per SMEM k-tile
#define NT 128
#define ROWB 144          // SMEM row stride bytes (128 payload + 16 pad)

// prep_kernel role layout
#define GATE_BLOCKS (NTOK / 8)                          // 512
#define T1_BLOCKS   ((HIDDEN / 32) * (DIM / 64) * NEXP) // 16384
#define T2_BLOCKS   ((DIM / 32) * (HIDDEN / 64) * NEXP) // 16384

// ---------------- scratch (__device__ statics — alloc-free) ----------------
__device__ int    g_cnt[NEXP];
__device__ int    g_list[NEXP][NTOK];
__device__ float  g_gw[NEXP][NTOK];
__device__ __half g_xh[(size_t)NTOK * DIM];
__device__ __half g_h[(size_t)NTOK * 2 * HIDDEN];
__device__ __half g_W1t[(size_t)NEXP * HIDDEN * DIM];     // [e][n][k]
__device__ __half g_W2t[(size_t)NEXP * DIM * HIDDEN];

// ---------------- helpers ----------------
__device__ __forceinline__ uint32_t smem_u32(const void* p) {
    uint32_t a;
    asm("{ .reg .u64 t; cvta.to.shared.u64 t, %1; cvt.u32.u64 %0, t; }" : "=r"(a) : "l"(p));
    return a;
}
__device__ __forceinline__ void cp_async16(uint32_t dst, const void* src) {
    asm volatile("cp.async.cg.shared.global [%0], [%1], 16;" :: "r"(dst), "l"(src));
}
#define CP_COMMIT() asm volatile("cp.async.commit_group;" ::: "memory")
#define CP_WAIT1()  asm volatile("cp.async.wait_group 1;" ::: "memory")

__device__ __forceinline__ void ldsm_x4(uint32_t* r, uint32_t addr) {
    asm volatile("ldmatrix.sync.aligned.m8n8.x4.shared.b16 {%0,%1,%2,%3}, [%4];"
                 : "=r"(r[0]), "=r"(r[1]), "=r"(r[2]), "=r"(r[3]) : "r"(addr));
}
__device__ __forceinline__ void mma_f16(float* d, const uint32_t* a, uint32_t b0, uint32_t b1) {
    asm volatile(
        "mma.sync.aligned.m16n8k16.row.col.f32.f16.f16.f32 "
        "{%0,%1,%2,%3}, {%4,%5,%6,%7}, {%8,%9}, {%0,%1,%2,%3};"
        : "+f"(d[0]), "+f"(d[1]), "+f"(d[2]), "+f"(d[3])
        : "r"(a[0]), "r"(a[1]), "r"(a[2]), "r"(a[3]), "r"(b0), "r"(b1));
}

// ---------------- kernel 0: reset expert counters ----------------
__global__ void zero_cnt_kernel() {
    if (threadIdx.x < NEXP) g_cnt[threadIdx.x] = 0;
}

// ---------------- transpose body (identical math to proven R8 kernel) ----------------
__device__ __forceinline__ void transpose_body(const float* __restrict__ in,
                                               __half* __restrict__ out,
                                               int K, int N, int bx, int by, int e,
                                               float (*tile)[66]) {
    size_t base = (size_t)e * K * N;
    int n0 = bx * 32, k0 = by * 64;
    int tn = threadIdx.x & 31;
    int tk = threadIdx.x >> 5;          // 0..7
#pragma unroll
    for (int i = 0; i < 8; i++) {
        int k = tk + i * 8;
        tile[tn][k] = in[base + (size_t)(k0 + k) * N + n0 + tn];
    }
    __syncthreads();
    int w = threadIdx.x >> 5, lane = threadIdx.x & 31;
#pragma unroll
    for (int r = 0; r < 4; r++) {
        int n = w + r * 8;
        float2 v = *(const float2*)&tile[n][2 * lane];
        *(__half2*)(out + base + (size_t)(n0 + n) * K + k0 + 2 * lane) =
            __floats2half2_rn(v.x, v.y);
    }
}

// ---------------- merged prep kernel: gate+zero | W1 cvt | W2 cvt ----------------
__global__ void prep_kernel(const float* __restrict__ x,
                            const float* __restrict__ Wg,
                            const float* __restrict__ bg,
                            const float* __restrict__ W1,
                            const float* __restrict__ W2,
                            float* __restrict__ out) {
    __shared__ float tile[32][66];
    const int bid = blockIdx.x;

    if (bid >= GATE_BLOCKS) {
        int b = bid - GATE_BLOCKS;
        if (b < T1_BLOCKS) {
            int bx = b & 127, by = (b >> 7) & 15, e = b >> 11;
            transpose_body(W1, g_W1t, DIM, HIDDEN, bx, by, e, tile);
        } else {
            int b2 = b - T1_BLOCKS;
            int bx = b2 & 31, by = (b2 >> 5) & 63, e = b2 >> 11;
            transpose_body(W2, g_W2t, HIDDEN, DIM, bx, by, e, tile);
        }
        return;
    }

    // ---- gate role: 8 warps, 1 token per warp; fuses x fp16 cvt + out zeroing ----
    int warp = bid * 8 + (threadIdx.x >> 5);
    int lane = threadIdx.x & 31;

    const float4* xr4 = (const float4*)(x + (size_t)warp * DIM);
    __half2* xo = (__half2*)(g_xh + (size_t)warp * DIM);
    float4* oz = (float4*)(out + (size_t)warp * DIM);

    float acc[NEXP];
#pragma unroll
    for (int e = 0; e < NEXP; e++) acc[e] = 0.f;

#pragma unroll
    for (int it = 0; it < 8; it++) {
        int i4 = lane + it * 32;
        float4 xv = xr4[i4];
        xo[2 * i4]     = __floats2half2_rn(xv.x, xv.y);
        xo[2 * i4 + 1] = __floats2half2_rn(xv.z, xv.w);
        oz[i4] = make_float4(0.f, 0.f, 0.f, 0.f);
        const float* xs = (const float*)&xv;
#pragma unroll
        for (int c = 0; c < 4; c++) {
            float v = xs[c];
            const float4* w = reinterpret_cast<const float4*>(Wg + (size_t)(i4 * 4 + c) * NEXP);
            float4 w0 = w[0], w1 = w[1];
            acc[0] = fmaf(v, w0.x, acc[0]); acc[1] = fmaf(v, w0.y, acc[1]);
            acc[2] = fmaf(v, w0.z, acc[2]); acc[3] = fmaf(v, w0.w, acc[3]);
            acc[4] = fmaf(v, w1.x, acc[4]); acc[5] = fmaf(v, w1.y, acc[5]);
            acc[6] = fmaf(v, w1.z, acc[6]); acc[7] = fmaf(v, w1.w, acc[7]);
        }
    }
#pragma unroll
    for (int off = 16; off > 0; off >>= 1)
#pragma unroll
        for (int e = 0; e < NEXP; e++)
            acc[e] += __shfl_xor_sync(0xffffffffu, acc[e], off);

    if (lane == 0) {
        float lg[NEXP], mx = -1e30f;
#pragma unroll
        for (int e = 0; e < NEXP; e++) { lg[e] = acc[e] + bg[e]; mx = fmaxf(mx, lg[e]); }
        float p[NEXP], s = 0.f;
#pragma unroll
        for (int e = 0; e < NEXP; e++) { p[e] = expf(lg[e] - mx); s += p[e]; }
        float inv = 1.f / s;
        int i0 = 0;
#pragma unroll
        for (int e = 1; e < NEXP; e++) if (p[e] > p[i0]) i0 = e;
        int i1 = (i0 == 0) ? 1 : 0;
#pragma unroll
        for (int e = 0; e < NEXP; e++) if (e != i0 && p[e] > p[i1]) i1 = e;

        int pos0 = atomicAdd(&g_cnt[i0], 1);
        g_list[i0][pos0] = warp * 2 + 0;  g_gw[i0][pos0] = p[i0] * inv;
        int pos1 = atomicAdd(&g_cnt[i1], 1);
        g_list[i1][pos1] = warp * 2 + 1;  g_gw[i1][pos1] = p[i1] * inv;
    }
}

// ---------------- fp16 mma.sync expert GEMM (4 warps, 64x64 warp tile) ----------------
// MODE 0: A = gathered g_xh rows, B = W1t, epi: half(relu(acc+b1)) -> g_h
// MODE 1: A = gathered g_h rows,  B = W2t, epi: atomicAdd(out, gw*(acc+b2))
template<int MODE, int KDIM, int NCOLS>
__global__ void __launch_bounds__(NT, 2)
moe_mma(const __half* __restrict__ Asrc, const __half* __restrict__ Wt,
        const float* __restrict__ bias, float* __restrict__ out) {
    const int e   = blockIdx.z;
    const int cnt = g_cnt[e];
    const int m0  = blockIdx.x * BM;
    if (m0 >= cnt) return;

    extern __shared__ char smem[];
    int*   s_row = (int*)smem;                 // [128]
    float* s_gw  = (float*)(smem + 512);       // [128]
    const int TILE_B  = BM * ROWB;             // 18432 B
    const int STAGE_B = 2 * TILE_B;

    const int tid  = threadIdx.x;
    const int wid  = tid >> 5, lane = tid & 31;
    const int wm   = (wid >> 1) * 64;
    const int wn   = (wid & 1) * 64;
    const int g    = lane >> 2;
    const int tg   = lane & 3;

    for (int i = tid; i < BM; i += NT) {
        int r = m0 + i;
        if (r < cnt) { s_row[i] = g_list[e][r]; s_gw[i] = g_gw[e][r]; }
        else         { s_row[i] = -1;           s_gw[i] = 0.f; }
    }
    __syncthreads();

    const int gn0 = blockIdx.y * BN;
    const uint32_t tiles_b = smem_u32(smem) + 1024;

    const int lrow = tid >> 3, c8 = tid & 7;
    uint32_t a_off[8];
#pragma unroll
    for (int i = 0; i < 8; i++) {
        int p = s_row[lrow + i * 16];
        int arow = (p >= 0) ? (MODE == 0 ? (p >> 1) : p) : 0;
        a_off[i] = (uint32_t)arow * KDIM + c8 * 8;
    }
    const __half* b_base = Wt + ((size_t)e * NCOLS + gn0 + lrow) * KDIM + c8 * 8;
    const uint32_t a_dst0 = (uint32_t)(lrow * ROWB + c8 * 16);
    const uint32_t b_dst0 = (uint32_t)(TILE_B + lrow * ROWB + c8 * 16);
    const uint32_t rstep  = 16 * ROWB;

    const uint32_t a_lane = (uint32_t)((lane & 15) * ROWB + (lane >> 4) * 16);
    const int nloc  = (lane & 7) + ((lane >> 4) << 3);
    const uint32_t b_lane = (uint32_t)(nloc * ROWB + ((lane >> 3) & 1) * 16);

    float acc[4][8][4];
#pragma unroll
    for (int i = 0; i < 4; i++)
#pragma unroll
        for (int j = 0; j < 8; j++)
#pragma unroll
            for (int q = 0; q < 4; q++) acc[i][j][q] = 0.f;

    const int KT = KDIM / BKH;

#pragma unroll
    for (int i = 0; i < 8; i++) {
        cp_async16(tiles_b + a_dst0 + i * rstep, Asrc + a_off[i]);
        cp_async16(tiles_b + b_dst0 + i * rstep, b_base + (size_t)i * 16 * KDIM);
    }
    CP_COMMIT();

#pragma unroll 1
    for (int t = 0; t < KT; ++t) {
        if (t + 1 < KT) {
            const uint32_t sb = tiles_b + ((t + 1) & 1) * STAGE_B;
            const int k1 = (t + 1) * BKH;
#pragma unroll
            for (int i = 0; i < 8; i++) {
                cp_async16(sb + a_dst0 + i * rstep, Asrc + a_off[i] + k1);
                cp_async16(sb + b_dst0 + i * rstep, b_base + (size_t)i * 16 * KDIM + k1);
            }
        }
        CP_COMMIT();
        CP_WAIT1();
        __syncthreads();

        const uint32_t As_b = tiles_b + (t & 1) * STAGE_B;
        const uint32_t Bs_b = As_b + TILE_B;
#pragma unroll
        for (int s = 0; s < 4; s++) {
            const uint32_t kb = s * 32;
            uint32_t af[4][4];
#pragma unroll
            for (int i = 0; i < 4; i++)
                ldsm_x4(af[i], As_b + (uint32_t)(wm + 16 * i) * ROWB + kb + a_lane);
            uint32_t bf[4][4];
#pragma unroll
            for (int j2 = 0; j2 < 4; j2++)
                ldsm_x4(bf[j2], Bs_b + (uint32_t)(wn + 16 * j2) * ROWB + kb + b_lane);
#pragma unroll
            for (int i = 0; i < 4; i++)
#pragma unroll
                for (int j2 = 0; j2 < 4; j2++) {
                    mma_f16(acc[i][2 * j2],     af[i], bf[j2][0], bf[j2][1]);
                    mma_f16(acc[i][2 * j2 + 1], af[i], bf[j2][2], bf[j2][3]);
                }
        }
        __syncthreads();
    }

    // ---------------- epilogue ----------------
#pragma unroll
    for (int i = 0; i < 4; i++) {
        const int rl = wm + i * 16 + g;
        const int pl = s_row[rl],  ph = s_row[rl + 8];
        const float gl = s_gw[rl], gh2 = s_gw[rl + 8];
#pragma unroll
        for (int j = 0; j < 8; j++) {
            const int n = gn0 + wn + j * 8 + 2 * tg;
            const float2 bb = *(const float2*)(bias + (size_t)e * NCOLS + n);
            if (MODE == 0) {
                if (pl >= 0)
                    *(__half2*)(g_h + (size_t)pl * HIDDEN + n) =
                        __floats2half2_rn(fmaxf(acc[i][j][0] + bb.x, 0.f),
                                          fmaxf(acc[i][j][1] + bb.y, 0.f));
                if (ph >= 0)
                    *(__half2*)(g_h + (size_t)ph * HIDDEN + n) =
                        __floats2half2_rn(fmaxf(acc[i][j][2] + bb.x, 0.f),
                                          fmaxf(acc[i][j][3] + bb.y, 0.f));
            } else {
                // exactly two commutative addends onto 0.0f per element ->
                // bitwise deterministic regardless of atomic order.
                if (pl >= 0) {
                    float* op = out + (size_t)(pl >> 1) * DIM + n;
                    atomicAdd(op,     gl * (acc[i][j][0] + bb.x));
                    atomicAdd(op + 1, gl * (acc[i][j][1] + bb.y));
                }
                if (ph >= 0) {
                    float* op = out + (size_t)(ph >> 1) * DIM + n;
                    atomicAdd(op,     gh2 * (acc[i][j][2] + bb.x));
                    atomicAdd(op + 1, gh2 * (acc[i][j][3] + bb.y));
                }
            }
        }
    }
}

// ---------------- launch ----------------
static constexpr int SMEM_BYTES = 1024 + 2 * 2 * BM * ROWB;   // 74752

extern "C" void kernel_launch(void* const* d_in, const int* in_sizes, int n_in,
                              void* d_out, int out_size) {
    const float* x  = (const float*)d_in[0];
    const float* Wg = (const float*)d_in[1];
    const float* bg = (const float*)d_in[2];
    const float* W1 = (const float*)d_in[3];
    const float* b1 = (const float*)d_in[4];
    const float* W2 = (const float*)d_in[5];
    const float* b2 = (const float*)d_in[6];
    float* out = (float*)d_out;

    cudaFuncSetAttribute(moe_mma<0, DIM, HIDDEN>,
                         cudaFuncAttributeMaxDynamicSharedMemorySize, SMEM_BYTES);
    cudaFuncSetAttribute(moe_mma<1, HIDDEN, DIM>,
                         cudaFuncAttributeMaxDynamicSharedMemorySize, SMEM_BYTES);

    __half* W1t; cudaGetSymbolAddress((void**)&W1t, g_W1t);
    __half* W2t; cudaGetSymbolAddress((void**)&W2t, g_W2t);
    __half* xh;  cudaGetSymbolAddress((void**)&xh,  g_xh);
    __half* gh;  cudaGetSymbolAddress((void**)&gh,  g_h);

    zero_cnt_kernel<<<1, 32>>>();
    prep_kernel<<<GATE_BLOCKS + T1_BLOCKS + T2_BLOCKS, 256>>>(x, Wg, bg, W1, W2, out);
    moe_mma<0, DIM, HIDDEN><<<dim3(NTOK / BM, HIDDEN / BN, NEXP), NT, SMEM_BYTES>>>(xh, W1t, b1, nullptr);
    moe_mma<1, HIDDEN, DIM><<<dim3(NTOK / BM, DIM / BN, NEXP), NT, SMEM_BYTES>>>(gh, W2t, b2, out);
}

// round 10
// speedup vs baseline: 1.2272x; 1.1020x over previous
#include <cuda_runtime.h>
#include <cuda_fp16.h>
#include <math.h>
#include <stdint.h>

#define NTOK   4096
#define DIM    1024
#define NEXP   8
#define HIDDEN 4096

#define BM 128
#define BN 128
#define BKH 64            // K halfs per k-tile
#define NT 128
#define ROWA 144          // A SMEM row stride bytes (128 payload + 16 pad)
#define ROWBB 272         // B SMEM row stride bytes (256 payload + 16 pad; 272%128=16)

#define TILE_A  (BM * ROWA)          // 18432
#define TILE_BB (BKH * ROWBB)        // 17408
#define STAGE_B (TILE_A + TILE_BB)   // 35840

#define GATE_BLOCKS 512
#define W1CVT_BLOCKS 2048            // 33.5M elems / (256 thr * 64)
#define G1_BLOCKS  8192              // 32m * 32n * 8e
#define W2CVT_BLOCKS 2048            // 33.5M elems / (128 thr * 128)

// ---------------- scratch (__device__ statics — alloc-free) ----------------
__device__ int    g_cnt[NEXP];
__device__ int    g_list[NEXP][NTOK];
__device__ float  g_gw[NEXP][NTOK];
__device__ __half g_xh[(size_t)NTOK * DIM];
__device__ __half g_h[(size_t)NTOK * 2 * HIDDEN];
__device__ __half g_W1h[(size_t)NEXP * DIM * HIDDEN];     // [e][k][n] fp16 (straight cvt)
__device__ __half g_W2h[(size_t)NEXP * HIDDEN * DIM];     // [e][k][n] fp16

// ---------------- helpers ----------------
__device__ __forceinline__ uint32_t smem_u32(const void* p) {
    uint32_t a;
    asm("{ .reg .u64 t; cvta.to.shared.u64 t, %1; cvt.u32.u64 %0, t; }" : "=r"(a) : "l"(p));
    return a;
}
__device__ __forceinline__ void cp_async16(uint32_t dst, const void* src) {
    asm volatile("cp.async.cg.shared.global [%0], [%1], 16;" :: "r"(dst), "l"(src));
}
#define CP_COMMIT() asm volatile("cp.async.commit_group;" ::: "memory")
#define CP_WAIT1()  asm volatile("cp.async.wait_group 1;" ::: "memory")

__device__ __forceinline__ void ldsm_x4(uint32_t* r, uint32_t addr) {
    asm volatile("ldmatrix.sync.aligned.m8n8.x4.shared.b16 {%0,%1,%2,%3}, [%4];"
                 : "=r"(r[0]), "=r"(r[1]), "=r"(r[2]), "=r"(r[3]) : "r"(addr));
}
__device__ __forceinline__ void ldsm_x4_t(uint32_t* r, uint32_t addr) {
    asm volatile("ldmatrix.sync.aligned.m8n8.x4.trans.shared.b16 {%0,%1,%2,%3}, [%4];"
                 : "=r"(r[0]), "=r"(r[1]), "=r"(r[2]), "=r"(r[3]) : "r"(addr));
}
__device__ __forceinline__ void mma_f16(float* d, const uint32_t* a, uint32_t b0, uint32_t b1) {
    asm volatile(
        "mma.sync.aligned.m16n8k16.row.col.f32.f16.f16.f32 "
        "{%0,%1,%2,%3}, {%4,%5,%6,%7}, {%8,%9}, {%0,%1,%2,%3};"
        : "+f"(d[0]), "+f"(d[1]), "+f"(d[2]), "+f"(d[3])
        : "r"(a[0]), "r"(a[1]), "r"(a[2]), "r"(a[3]), "r"(b0), "r"(b1));
}

// ---------------- kernel 0: reset expert counters ----------------
__global__ void zero_cnt_kernel() {
    if (threadIdx.x < NEXP) g_cnt[threadIdx.x] = 0;
}

// ---------------- prep: gate(+x cvt + out zero) | W1 straight cvt ----------------
__global__ void prep_kernel(const float* __restrict__ x,
                            const float* __restrict__ Wg,
                            const float* __restrict__ bg,
                            const float* __restrict__ W1,
                            float* __restrict__ out) {
    const int bid = blockIdx.x;
    const int tid = threadIdx.x;

    if (bid >= GATE_BLOCKS) {
        // ---- W1 cvt role: fp32 [e][k][n] -> fp16 same layout ----
        size_t base = (size_t)(bid - GATE_BLOCKS) * 16384 + (size_t)tid * 4;
#pragma unroll
        for (int j = 0; j < 16; j++) {
            size_t idx = base + (size_t)j * 1024;
            float4 v = *(const float4*)(W1 + idx);
            __half2 h0 = __floats2half2_rn(v.x, v.y);
            __half2 h1 = __floats2half2_rn(v.z, v.w);
            *(uint2*)(g_W1h + idx) =
                make_uint2(*(uint32_t*)&h0, *(uint32_t*)&h1);
        }
        return;
    }

    // ---- gate role: 8 warps, 1 token per warp; fused x cvt + out zero ----
    int warp = bid * 8 + (tid >> 5);
    int lane = tid & 31;

    const float4* xr4 = (const float4*)(x + (size_t)warp * DIM);
    __half2* xo = (__half2*)(g_xh + (size_t)warp * DIM);
    float4* oz = (float4*)(out + (size_t)warp * DIM);

    float acc[NEXP];
#pragma unroll
    for (int e = 0; e < NEXP; e++) acc[e] = 0.f;

#pragma unroll
    for (int it = 0; it < 8; it++) {
        int i4 = lane + it * 32;
        float4 xv = xr4[i4];
        xo[2 * i4]     = __floats2half2_rn(xv.x, xv.y);
        xo[2 * i4 + 1] = __floats2half2_rn(xv.z, xv.w);
        oz[i4] = make_float4(0.f, 0.f, 0.f, 0.f);
        const float* xs = (const float*)&xv;
#pragma unroll
        for (int c = 0; c < 4; c++) {
            float v = xs[c];
            const float4* w = reinterpret_cast<const float4*>(Wg + (size_t)(i4 * 4 + c) * NEXP);
            float4 w0 = w[0], w1 = w[1];
            acc[0] = fmaf(v, w0.x, acc[0]); acc[1] = fmaf(v, w0.y, acc[1]);
            acc[2] = fmaf(v, w0.z, acc[2]); acc[3] = fmaf(v, w0.w, acc[3]);
            acc[4] = fmaf(v, w1.x, acc[4]); acc[5] = fmaf(v, w1.y, acc[5]);
            acc[6] = fmaf(v, w1.z, acc[6]); acc[7] = fmaf(v, w1.w, acc[7]);
        }
    }
#pragma unroll
    for (int off = 16; off > 0; off >>= 1)
#pragma unroll
        for (int e = 0; e < NEXP; e++)
            acc[e] += __shfl_xor_sync(0xffffffffu, acc[e], off);

    if (lane == 0) {
        float lg[NEXP], mx = -1e30f;
#pragma unroll
        for (int e = 0; e < NEXP; e++) { lg[e] = acc[e] + bg[e]; mx = fmaxf(mx, lg[e]); }
        float p[NEXP], s = 0.f;
#pragma unroll
        for (int e = 0; e < NEXP; e++) { p[e] = expf(lg[e] - mx); s += p[e]; }
        float inv = 1.f / s;
        int i0 = 0;
#pragma unroll
        for (int e = 1; e < NEXP; e++) if (p[e] > p[i0]) i0 = e;
        int i1 = (i0 == 0) ? 1 : 0;
#pragma unroll
        for (int e = 0; e < NEXP; e++) if (e != i0 && p[e] > p[i1]) i1 = e;

        int pos0 = atomicAdd(&g_cnt[i0], 1);
        g_list[i0][pos0] = warp * 2 + 0;  g_gw[i0][pos0] = p[i0] * inv;
        int pos1 = atomicAdd(&g_cnt[i1], 1);
        g_list[i1][pos1] = warp * 2 + 1;  g_gw[i1][pos1] = p[i1] * inv;
    }
}

// ---------------- fp16 mma GEMM, B from K-major [k][n] via ldsm.trans ----------------
// MODE 0: A = gathered g_xh, B = g_W1h, epi: half(relu(acc+b1)) -> g_h
//         + extra CTAs (bid >= G1_BLOCKS) do the W2 fp32->fp16 cvt, overlapped.
// MODE 1: A = gathered g_h,  B = g_W2h, epi: atomicAdd(out, gw*(acc+b2))
template<int MODE, int KDIM, int NCOLS, int LOGN>
__global__ void __launch_bounds__(NT, 2)
moe_mma(const __half* __restrict__ Asrc, const __half* __restrict__ Wh,
        const float* __restrict__ bias, float* __restrict__ out,
        const float* __restrict__ cvt_src, __half* __restrict__ cvt_dst) {
    const int bid = blockIdx.x;
    const int tid = threadIdx.x;

    if (MODE == 0 && bid >= G1_BLOCKS) {
        // ---- W2 cvt role, overlapped with GEMM1 ----
        size_t base = (size_t)(bid - G1_BLOCKS) * 16384 + (size_t)tid * 4;
#pragma unroll
        for (int j = 0; j < 32; j++) {
            size_t idx = base + (size_t)j * 512;
            float4 v = *(const float4*)(cvt_src + idx);
            __half2 h0 = __floats2half2_rn(v.x, v.y);
            __half2 h1 = __floats2half2_rn(v.z, v.w);
            *(uint2*)(cvt_dst + idx) =
                make_uint2(*(uint32_t*)&h0, *(uint32_t*)&h1);
        }
        return;
    }

    const int e   = bid >> (5 + LOGN);
    const int cnt = g_cnt[e];
    const int m0  = (bid & 31) * BM;
    if (m0 >= cnt) return;
    const int gn0 = ((bid >> 5) & ((1 << LOGN) - 1)) * BN;

    extern __shared__ char smem[];
    int*   s_row = (int*)smem;                 // [128]
    float* s_gw  = (float*)(smem + 512);       // [128]

    const int wid  = tid >> 5, lane = tid & 31;
    const int wm   = (wid >> 1) * 64;
    const int wn   = (wid & 1) * 64;
    const int g    = lane >> 2;
    const int tg   = lane & 3;

    for (int i = tid; i < BM; i += NT) {
        int r = m0 + i;
        if (r < cnt) { s_row[i] = g_list[e][r]; s_gw[i] = g_gw[e][r]; }
        else         { s_row[i] = -1;           s_gw[i] = 0.f; }
    }
    __syncthreads();

    const uint32_t tiles_b = smem_u32(smem) + 1024;

    // A loader: 8 chunks of 16B; chunk i -> row lrow+16i, col c8
    const int lrow = tid >> 3, c8 = tid & 7;
    uint32_t a_off[8];
#pragma unroll
    for (int i = 0; i < 8; i++) {
        int p = s_row[lrow + i * 16];
        int arow = (p >= 0) ? (MODE == 0 ? (p >> 1) : p) : 0;
        a_off[i] = (uint32_t)arow * KDIM + c8 * 8;
    }
    const uint32_t a_dst0 = (uint32_t)(lrow * ROWA + c8 * 16);
    const uint32_t rstepA = 16 * ROWA;

    // B loader (K-major): 8 chunks; chunk i -> k-row brow+8i, col16 bc16
    const int brow = tid >> 4, bc16 = tid & 15;
    const __half* b_base = Wh + ((size_t)e * KDIM + brow) * NCOLS + gn0 + bc16 * 8;
    const uint32_t b_dst0 = (uint32_t)(TILE_A + brow * ROWBB + bc16 * 16);
    const uint32_t bstep  = 8 * ROWBB;          // 8 k-rows in smem bytes

    // LDSM lane addressing
    const uint32_t a_lane = (uint32_t)((lane & 15) * ROWA + (lane >> 4) * 16);
    const uint32_t bt_row = (uint32_t)(lane & 15);
    const uint32_t bt_col = (uint32_t)(((lane >> 4) & 1) * 16);

    float acc[4][8][4];
#pragma unroll
    for (int i = 0; i < 4; i++)
#pragma unroll
        for (int j = 0; j < 8; j++)
#pragma unroll
            for (int q = 0; q < 4; q++) acc[i][j][q] = 0.f;

    const int KT = KDIM / BKH;

#pragma unroll
    for (int i = 0; i < 8; i++) {
        cp_async16(tiles_b + a_dst0 + i * rstepA, Asrc + a_off[i]);
        cp_async16(tiles_b + b_dst0 + i * bstep, b_base + (size_t)(8 * i) * NCOLS);
    }
    CP_COMMIT();

#pragma unroll 1
    for (int t = 0; t < KT; ++t) {
        if (t + 1 < KT) {
            const uint32_t sb = tiles_b + ((t + 1) & 1) * STAGE_B;
            const int k1 = (t + 1) * BKH;
            const __half* bsrc = b_base + (size_t)k1 * NCOLS;
#pragma unroll
            for (int i = 0; i < 8; i++) {
                cp_async16(sb + a_dst0 + i * rstepA, Asrc + a_off[i] + k1);
                cp_async16(sb + b_dst0 + i * bstep, bsrc + (size_t)(8 * i) * NCOLS);
            }
        }
        CP_COMMIT();
        CP_WAIT1();
        __syncthreads();

        const uint32_t As_b = tiles_b + (t & 1) * STAGE_B;
        const uint32_t Bs_b = As_b + TILE_A;
#pragma unroll
        for (int s = 0; s < 4; s++) {
            uint32_t af[4][4];
#pragma unroll
            for (int i = 0; i < 4; i++)
                ldsm_x4(af[i], As_b + (uint32_t)(wm + 16 * i) * ROWA + s * 32 + a_lane);
            uint32_t bf[4][4];
#pragma unroll
            for (int j2 = 0; j2 < 4; j2++)
                ldsm_x4_t(bf[j2], Bs_b + (uint32_t)(s * 16 + bt_row) * ROWBB
                                   + (uint32_t)(wn * 2 + j2 * 32) + bt_col);
#pragma unroll
            for (int i = 0; i < 4; i++)
#pragma unroll
                for (int j2 = 0; j2 < 4; j2++) {
                    mma_f16(acc[i][2 * j2],     af[i], bf[j2][0], bf[j2][1]);
                    mma_f16(acc[i][2 * j2 + 1], af[i], bf[j2][2], bf[j2][3]);
                }
        }
        __syncthreads();
    }

    // ---------------- epilogue ----------------
#pragma unroll
    for (int i = 0; i < 4; i++) {
        const int rl = wm + i * 16 + g;
        const int pl = s_row[rl],  ph = s_row[rl + 8];
        const float gl = s_gw[rl], gh2 = s_gw[rl + 8];
#pragma unroll
        for (int j = 0; j < 8; j++) {
            const int n = gn0 + wn + j * 8 + 2 * tg;
            const float2 bb = *(const float2*)(bias + (size_t)e * NCOLS + n);
            if (MODE == 0) {
                if (pl >= 0)
                    *(__half2*)(g_h + (size_t)pl * HIDDEN + n) =
                        __floats2half2_rn(fmaxf(acc[i][j][0] + bb.x, 0.f),
                                          fmaxf(acc[i][j][1] + bb.y, 0.f));
                if (ph >= 0)
                    *(__half2*)(g_h + (size_t)ph * HIDDEN + n) =
                        __floats2half2_rn(fmaxf(acc[i][j][2] + bb.x, 0.f),
                                          fmaxf(acc[i][j][3] + bb.y, 0.f));
            } else {
                // exactly two commutative addends onto 0.0f per element ->
                // bitwise deterministic regardless of atomic order.
                if (pl >= 0) {
                    float* op = out + (size_t)(pl >> 1) * DIM + n;
                    atomicAdd(op,     gl * (acc[i][j][0] + bb.x));
                    atomicAdd(op + 1, gl * (acc[i][j][1] + bb.y));
                }
                if (ph >= 0) {
                    float* op = out + (size_t)(ph >> 1) * DIM + n;
                    atomicAdd(op,     gh2 * (acc[i][j][2] + bb.x));
                    atomicAdd(op + 1, gh2 * (acc[i][j][3] + bb.y));
                }
            }
        }
    }
}

// ---------------- launch ----------------
static constexpr int SMEM_BYTES = 1024 + 2 * STAGE_B;   // 72704

extern "C" void kernel_launch(void* const* d_in, const int* in_sizes, int n_in,
                              void* d_out, int out_size) {
    const float* x  = (const float*)d_in[0];
    const float* Wg = (const float*)d_in[1];
    const float* bg = (const float*)d_in[2];
    const float* W1 = (const float*)d_in[3];
    const float* b1 = (const float*)d_in[4];
    const float* W2 = (const float*)d_in[5];
    const float* b2 = (const float*)d_in[6];
    float* out = (float*)d_out;

    cudaFuncSetAttribute(moe_mma<0, DIM, HIDDEN, 5>,
                         cudaFuncAttributeMaxDynamicSharedMemorySize, SMEM_BYTES);
    cudaFuncSetAttribute(moe_mma<1, HIDDEN, DIM, 3>,
                         cudaFuncAttributeMaxDynamicSharedMemorySize, SMEM_BYTES);

    __half* W1h; cudaGetSymbolAddress((void**)&W1h, g_W1h);
    __half* W2h; cudaGetSymbolAddress((void**)&W2h, g_W2h);
    __half* xh;  cudaGetSymbolAddress((void**)&xh,  g_xh);
    __half* gh;  cudaGetSymbolAddress((void**)&gh,  g_h);

    zero_cnt_kernel<<<1, 32>>>();
    prep_kernel<<<GATE_BLOCKS + W1CVT_BLOCKS, 256>>>(x, Wg, bg, W1, out);
    moe_mma<0, DIM, HIDDEN, 5><<<G1_BLOCKS + W2CVT_BLOCKS, NT, SMEM_BYTES>>>(
        xh, W1h, b1, nullptr, W2, W2h);
    moe_mma<1, HIDDEN, DIM, 3><<<32 * 8 * NEXP, NT, SMEM_BYTES>>>(
        gh, W2h, b2, out, nullptr, nullptr);
}

// round 11
// speedup vs baseline: 1.2315x; 1.0035x over previous
#include <cuda_runtime.h>
#include <cuda_fp16.h>
#include <math.h>
#include <stdint.h>

#define NTOK   4096
#define DIM    1024
#define NEXP   8
#define HIDDEN 4096

#define BM 128
#define BN 128
#define BKH 64            // K halfs per k-tile
#define NT 256
#define ROWA 144          // A SMEM row stride bytes (128 payload + 16 pad)
#define ROWBB 272         // B SMEM row stride bytes (256 payload + 16 pad)

#define TILE_A  (BM * ROWA)          // 18432
#define TILE_BB (BKH * ROWBB)        // 17408
#define STAGE_B (TILE_A + TILE_BB)   // 35840
#define NSTAGE  3

#define GATE_BLOCKS 512
#define W1CVT_BLOCKS 2048
#define G1_BLOCKS  8192              // 32m * 32n * 8e
#define W2CVT_BLOCKS 2048

// ---------------- scratch (__device__ statics — alloc-free) ----------------
__device__ int    g_cnt[NEXP];
__device__ int    g_list[NEXP][NTOK];
__device__ float  g_gw[NEXP][NTOK];
__device__ __half g_xh[(size_t)NTOK * DIM];
__device__ __half g_h[(size_t)NTOK * 2 * HIDDEN];
__device__ __half g_W1h[(size_t)NEXP * DIM * HIDDEN];     // [e][k][n] fp16
__device__ __half g_W2h[(size_t)NEXP * HIDDEN * DIM];     // [e][k][n] fp16

// ---------------- helpers ----------------
__device__ __forceinline__ uint32_t smem_u32(const void* p) {
    uint32_t a;
    asm("{ .reg .u64 t; cvta.to.shared.u64 t, %1; cvt.u32.u64 %0, t; }" : "=r"(a) : "l"(p));
    return a;
}
__device__ __forceinline__ void cp_async16(uint32_t dst, const void* src) {
    asm volatile("cp.async.cg.shared.global [%0], [%1], 16;" :: "r"(dst), "l"(src));
}
#define CP_COMMIT() asm volatile("cp.async.commit_group;" ::: "memory")
#define CP_WAIT2()  asm volatile("cp.async.wait_group 2;" ::: "memory")

__device__ __forceinline__ void ldsm_x4(uint32_t* r, uint32_t addr) {
    asm volatile("ldmatrix.sync.aligned.m8n8.x4.shared.b16 {%0,%1,%2,%3}, [%4];"
                 : "=r"(r[0]), "=r"(r[1]), "=r"(r[2]), "=r"(r[3]) : "r"(addr));
}
__device__ __forceinline__ void ldsm_x4_t(uint32_t* r, uint32_t addr) {
    asm volatile("ldmatrix.sync.aligned.m8n8.x4.trans.shared.b16 {%0,%1,%2,%3}, [%4];"
                 : "=r"(r[0]), "=r"(r[1]), "=r"(r[2]), "=r"(r[3]) : "r"(addr));
}
__device__ __forceinline__ void mma_f16(float* d, const uint32_t* a, uint32_t b0, uint32_t b1) {
    asm volatile(
        "mma.sync.aligned.m16n8k16.row.col.f32.f16.f16.f32 "
        "{%0,%1,%2,%3}, {%4,%5,%6,%7}, {%8,%9}, {%0,%1,%2,%3};"
        : "+f"(d[0]), "+f"(d[1]), "+f"(d[2]), "+f"(d[3])
        : "r"(a[0]), "r"(a[1]), "r"(a[2]), "r"(a[3]), "r"(b0), "r"(b1));
}

// ---------------- kernel 0: reset expert counters ----------------
__global__ void zero_cnt_kernel() {
    if (threadIdx.x < NEXP) g_cnt[threadIdx.x] = 0;
}

// ---------------- prep: gate(+x cvt + out zero) | W1 straight cvt ----------------
__global__ void prep_kernel(const float* __restrict__ x,
                            const float* __restrict__ Wg,
                            const float* __restrict__ bg,
                            const float* __restrict__ W1,
                            float* __restrict__ out) {
    const int bid = blockIdx.x;
    const int tid = threadIdx.x;

    if (bid >= GATE_BLOCKS) {
        size_t base = (size_t)(bid - GATE_BLOCKS) * 16384 + (size_t)tid * 4;
#pragma unroll
        for (int j = 0; j < 16; j++) {
            size_t idx = base + (size_t)j * 1024;
            float4 v = *(const float4*)(W1 + idx);
            __half2 h0 = __floats2half2_rn(v.x, v.y);
            __half2 h1 = __floats2half2_rn(v.z, v.w);
            *(uint2*)(g_W1h + idx) = make_uint2(*(uint32_t*)&h0, *(uint32_t*)&h1);
        }
        return;
    }

    int warp = bid * 8 + (tid >> 5);
    int lane = tid & 31;

    const float4* xr4 = (const float4*)(x + (size_t)warp * DIM);
    __half2* xo = (__half2*)(g_xh + (size_t)warp * DIM);
    float4* oz = (float4*)(out + (size_t)warp * DIM);

    float acc[NEXP];
#pragma unroll
    for (int e = 0; e < NEXP; e++) acc[e] = 0.f;

#pragma unroll
    for (int it = 0; it < 8; it++) {
        int i4 = lane + it * 32;
        float4 xv = xr4[i4];
        xo[2 * i4]     = __floats2half2_rn(xv.x, xv.y);
        xo[2 * i4 + 1] = __floats2half2_rn(xv.z, xv.w);
        oz[i4] = make_float4(0.f, 0.f, 0.f, 0.f);
        const float* xs = (const float*)&xv;
#pragma unroll
        for (int c = 0; c < 4; c++) {
            float v = xs[c];
            const float4* w = reinterpret_cast<const float4*>(Wg + (size_t)(i4 * 4 + c) * NEXP);
            float4 w0 = w[0], w1 = w[1];
            acc[0] = fmaf(v, w0.x, acc[0]); acc[1] = fmaf(v, w0.y, acc[1]);
            acc[2] = fmaf(v, w0.z, acc[2]); acc[3] = fmaf(v, w0.w, acc[3]);
            acc[4] = fmaf(v, w1.x, acc[4]); acc[5] = fmaf(v, w1.y, acc[5]);
            acc[6] = fmaf(v, w1.z, acc[6]); acc[7] = fmaf(v, w1.w, acc[7]);
        }
    }
#pragma unroll
    for (int off = 16; off > 0; off >>= 1)
#pragma unroll
        for (int e = 0; e < NEXP; e++)
            acc[e] += __shfl_xor_sync(0xffffffffu, acc[e], off);

    if (lane == 0) {
        float lg[NEXP], mx = -1e30f;
#pragma unroll
        for (int e = 0; e < NEXP; e++) { lg[e] = acc[e] + bg[e]; mx = fmaxf(mx, lg[e]); }
        float p[NEXP], s = 0.f;
#pragma unroll
        for (int e = 0; e < NEXP; e++) { p[e] = expf(lg[e] - mx); s += p[e]; }
        float inv = 1.f / s;
        int i0 = 0;
#pragma unroll
        for (int e = 1; e < NEXP; e++) if (p[e] > p[i0]) i0 = e;
        int i1 = (i0 == 0) ? 1 : 0;
#pragma unroll
        for (int e = 0; e < NEXP; e++) if (e != i0 && p[e] > p[i1]) i1 = e;

        int pos0 = atomicAdd(&g_cnt[i0], 1);
        g_list[i0][pos0] = warp * 2 + 0;  g_gw[i0][pos0] = p[i0] * inv;
        int pos1 = atomicAdd(&g_cnt[i1], 1);
        g_list[i1][pos1] = warp * 2 + 1;  g_gw[i1][pos1] = p[i1] * inv;
    }
}

// ---------------- fp16 mma GEMM: 8 warps (64x32 tiles), 3-stage pipeline ----------------
// MODE 0: A = gathered g_xh, B = g_W1h, epi: half(relu(acc+b1)) -> g_h  (+W2 cvt CTAs)
// MODE 1: A = gathered g_h,  B = g_W2h, epi: atomicAdd(out, gw*(acc+b2))
template<int MODE, int KDIM, int NCOLS, int LOGN>
__global__ void __launch_bounds__(NT, 2)
moe_mma(const __half* __restrict__ Asrc, const __half* __restrict__ Wh,
        const float* __restrict__ bias, float* __restrict__ out,
        const float* __restrict__ cvt_src, __half* __restrict__ cvt_dst) {
    const int bid = blockIdx.x;
    const int tid = threadIdx.x;

    if (MODE == 0 && bid >= G1_BLOCKS) {
        size_t base = (size_t)(bid - G1_BLOCKS) * 16384 + (size_t)tid * 4;
#pragma unroll
        for (int j = 0; j < 16; j++) {
            size_t idx = base + (size_t)j * 1024;
            float4 v = *(const float4*)(cvt_src + idx);
            __half2 h0 = __floats2half2_rn(v.x, v.y);
            __half2 h1 = __floats2half2_rn(v.z, v.w);
            *(uint2*)(cvt_dst + idx) = make_uint2(*(uint32_t*)&h0, *(uint32_t*)&h1);
        }
        return;
    }

    const int e   = bid >> (5 + LOGN);
    const int cnt = g_cnt[e];
    const int m0  = (bid & 31) * BM;
    if (m0 >= cnt) return;
    const int gn0 = ((bid >> 5) & ((1 << LOGN) - 1)) * BN;

    extern __shared__ char smem[];
    int*   s_row = (int*)smem;                 // [128]
    float* s_gw  = (float*)(smem + 512);       // [128]

    const int wid  = tid >> 5, lane = tid & 31;
    const int wm   = (wid >> 2) * 64;          // 0,64
    const int wn   = (wid & 3) * 32;           // 0,32,64,96
    const int g    = lane >> 2;
    const int tg   = lane & 3;

    for (int i = tid; i < BM; i += NT) {
        int r = m0 + i;
        if (r < cnt) { s_row[i] = g_list[e][r]; s_gw[i] = g_gw[e][r]; }
        else         { s_row[i] = -1;           s_gw[i] = 0.f; }
    }
    __syncthreads();

    const uint32_t tiles_b = smem_u32(smem) + 1024;

    // A loader: 4 chunks of 16B; chunk i -> row lrow+32i, col c8
    const int lrow = tid >> 3, c8 = tid & 7;
    uint32_t a_off[4];
#pragma unroll
    for (int i = 0; i < 4; i++) {
        int p = s_row[lrow + i * 32];
        int arow = (p >= 0) ? (MODE == 0 ? (p >> 1) : p) : 0;
        a_off[i] = (uint32_t)arow * KDIM + c8 * 8;
    }
    const uint32_t a_dst0 = (uint32_t)(lrow * ROWA + c8 * 16);
    const uint32_t rstepA = 32 * ROWA;

    // B loader (K-major): 4 chunks; chunk i -> k-row brow+16i
    const int brow = tid >> 4, bc16 = tid & 15;
    const __half* b_base = Wh + ((size_t)e * KDIM + brow) * NCOLS + gn0 + bc16 * 8;
    const uint32_t b_dst0 = (uint32_t)(TILE_A + brow * ROWBB + bc16 * 16);
    const uint32_t bstep  = 16 * ROWBB;

    // LDSM lane addressing
    const uint32_t a_lane = (uint32_t)((lane & 15) * ROWA + (lane >> 4) * 16);
    const uint32_t bt_row = (uint32_t)(lane & 15);
    const uint32_t bt_col = (uint32_t)(((lane >> 4) & 1) * 16);

    float acc[4][4][4];
#pragma unroll
    for (int i = 0; i < 4; i++)
#pragma unroll
        for (int j = 0; j < 4; j++)
#pragma unroll
            for (int q = 0; q < 4; q++) acc[i][j][q] = 0.f;

    const int KT = KDIM / BKH;

    // prologue: stages 0 and 1
#pragma unroll
    for (int st = 0; st < 2; st++) {
        const uint32_t sb = tiles_b + st * STAGE_B;
        const int kk = st * BKH;
#pragma unroll
        for (int i = 0; i < 4; i++) {
            cp_async16(sb + a_dst0 + i * rstepA, Asrc + a_off[i] + kk);
            cp_async16(sb + b_dst0 + i * bstep,
                       b_base + (size_t)(kk + 16 * i) * NCOLS);
        }
        CP_COMMIT();
    }

    int stc = 0;   // compute stage, stp = prefetch stage rotates +2
    int stp = 2;
#pragma unroll 1
    for (int t = 0; t < KT; ++t) {
        if (t + 2 < KT) {
            const uint32_t sb = tiles_b + stp * STAGE_B;
            const int k2 = (t + 2) * BKH;
#pragma unroll
            for (int i = 0; i < 4; i++) {
                cp_async16(sb + a_dst0 + i * rstepA, Asrc + a_off[i] + k2);
                cp_async16(sb + b_dst0 + i * bstep,
                           b_base + (size_t)(k2 + 16 * i) * NCOLS);
            }
        }
        CP_COMMIT();
        CP_WAIT2();
        __syncthreads();

        const uint32_t As_b = tiles_b + stc * STAGE_B;
        const uint32_t Bs_b = As_b + TILE_A;
#pragma unroll
        for (int s = 0; s < 4; s++) {
            uint32_t af[4][4];
#pragma unroll
            for (int i = 0; i < 4; i++)
                ldsm_x4(af[i], As_b + (uint32_t)(wm + 16 * i) * ROWA + s * 32 + a_lane);
            uint32_t bf[2][4];
#pragma unroll
            for (int j2 = 0; j2 < 2; j2++)
                ldsm_x4_t(bf[j2], Bs_b + (uint32_t)(s * 16 + bt_row) * ROWBB
                                   + (uint32_t)(wn * 2 + j2 * 32) + bt_col);
#pragma unroll
            for (int i = 0; i < 4; i++)
#pragma unroll
                for (int j2 = 0; j2 < 2; j2++) {
                    mma_f16(acc[i][2 * j2],     af[i], bf[j2][0], bf[j2][1]);
                    mma_f16(acc[i][2 * j2 + 1], af[i], bf[j2][2], bf[j2][3]);
                }
        }
        __syncthreads();
        stc = (stc == NSTAGE - 1) ? 0 : stc + 1;
        stp = (stp == NSTAGE - 1) ? 0 : stp + 1;
    }

    // ---------------- epilogue ----------------
#pragma unroll
    for (int i = 0; i < 4; i++) {
        const int rl = wm + i * 16 + g;
        const int pl = s_row[rl],  ph = s_row[rl + 8];
        const float gl = s_gw[rl], gh2 = s_gw[rl + 8];
#pragma unroll
        for (int j = 0; j < 4; j++) {
            const int n = gn0 + wn + j * 8 + 2 * tg;
            const float2 bb = *(const float2*)(bias + (size_t)e * NCOLS + n);
            if (MODE == 0) {
                if (pl >= 0)
                    *(__half2*)(g_h + (size_t)pl * HIDDEN + n) =
                        __floats2half2_rn(fmaxf(acc[i][j][0] + bb.x, 0.f),
                                          fmaxf(acc[i][j][1] + bb.y, 0.f));
                if (ph >= 0)
                    *(__half2*)(g_h + (size_t)ph * HIDDEN + n) =
                        __floats2half2_rn(fmaxf(acc[i][j][2] + bb.x, 0.f),
                                          fmaxf(acc[i][j][3] + bb.y, 0.f));
            } else {
                // two commutative addends onto 0.0f per element -> deterministic
                if (pl >= 0) {
                    float* op = out + (size_t)(pl >> 1) * DIM + n;
                    atomicAdd(op,     gl * (acc[i][j][0] + bb.x));
                    atomicAdd(op + 1, gl * (acc[i][j][1] + bb.y));
                }
                if (ph >= 0) {
                    float* op = out + (size_t)(ph >> 1) * DIM + n;
                    atomicAdd(op,     gh2 * (acc[i][j][2] + bb.x));
                    atomicAdd(op + 1, gh2 * (acc[i][j][3] + bb.y));
                }
            }
        }
    }
}

// ---------------- launch ----------------
static constexpr int SMEM_BYTES = 1024 + NSTAGE * STAGE_B;   // 108544

extern "C" void kernel_launch(void* const* d_in, const int* in_sizes, int n_in,
                              void* d_out, int out_size) {
    const float* x  = (const float*)d_in[0];
    const float* Wg = (const float*)d_in[1];
    const float* bg = (const float*)d_in[2];
    const float* W1 = (const float*)d_in[3];
    const float* b1 = (const float*)d_in[4];
    const float* W2 = (const float*)d_in[5];
    const float* b2 = (const float*)d_in[6];
    float* out = (float*)d_out;

    cudaFuncSetAttribute(moe_mma<0, DIM, HIDDEN, 5>,
                         cudaFuncAttributeMaxDynamicSharedMemorySize, SMEM_BYTES);
    cudaFuncSetAttribute(moe_mma<1, HIDDEN, DIM, 3>,
                         cudaFuncAttributeMaxDynamicSharedMemorySize, SMEM_BYTES);

    __half* W1h; cudaGetSymbolAddress((void**)&W1h, g_W1h);
    __half* W2h; cudaGetSymbolAddress((void**)&W2h, g_W2h);
    __half* xh;  cudaGetSymbolAddress((void**)&xh,  g_xh);
    __half* gh;  cudaGetSymbolAddress((void**)&gh,  g_h);

    zero_cnt_kernel<<<1, 32>>>();
    prep_kernel<<<GATE_BLOCKS + W1CVT_BLOCKS, 256>>>(x, Wg, bg, W1, out);
    moe_mma<0, DIM, HIDDEN, 5><<<G1_BLOCKS + W2CVT_BLOCKS, NT, SMEM_BYTES>>>(
        xh, W1h, b1, nullptr, W2, W2h);
    moe_mma<1, HIDDEN, DIM, 3><<<32 * 8 * NEXP, NT, SMEM_BYTES>>>(
        gh, W2h, b2, out, nullptr, nullptr);
}

// round 12
// speedup vs baseline: 1.2337x; 1.0017x over previous
#include <cuda_runtime.h>
#include <cuda_fp16.h>
#include <math.h>
#include <stdint.h>

#define NTOK   4096
#define DIM    1024
#define NEXP   8
#define HIDDEN 4096

#define BM 128
#define BN 128
#define BKH 64            // K halfs per k-tile
#define NT 256
#define ROWA 144          // A SMEM row stride bytes (128 payload + 16 pad)
#define ROWBB 272         // B SMEM row stride bytes (256 payload + 16 pad)

#define TILE_A  (BM * ROWA)          // 18432
#define TILE_BB (BKH * ROWBB)        // 17408
#define STAGE_B (TILE_A + TILE_BB)   // 35840
#define NSTAGE  3

#define GATE_BLOCKS 512
#define W1CVT_BLOCKS 2048
#define G1_BLOCKS  8192              // 32m * 32n * 8e
#define W2CVT_BLOCKS 2048

// ---------------- scratch (__device__ statics — alloc-free) ----------------
__device__ int    g_cnt[NEXP];
__device__ int    g_list[NEXP][NTOK];
__device__ float  g_gw[NEXP][NTOK];
__device__ __half g_xh[(size_t)NTOK * DIM];
__device__ __half g_h[(size_t)NTOK * 2 * HIDDEN];
__device__ __half g_W1h[(size_t)NEXP * DIM * HIDDEN];     // [e][k][n] fp16
__device__ __half g_W2h[(size_t)NEXP * HIDDEN * DIM];     // [e][k][n] fp16

// ---------------- helpers ----------------
__device__ __forceinline__ uint32_t smem_u32(const void* p) {
    uint32_t a;
    asm("{ .reg .u64 t; cvta.to.shared.u64 t, %1; cvt.u32.u64 %0, t; }" : "=r"(a) : "l"(p));
    return a;
}
__device__ __forceinline__ void cp_async16(uint32_t dst, const void* src) {
    asm volatile("cp.async.cg.shared.global [%0], [%1], 16;" :: "r"(dst), "l"(src));
}
#define CP_COMMIT() asm volatile("cp.async.commit_group;" ::: "memory")
#define CP_WAIT2()  asm volatile("cp.async.wait_group 2;" ::: "memory")

__device__ __forceinline__ void ldsm_x4(uint32_t* r, uint32_t addr) {
    asm volatile("ldmatrix.sync.aligned.m8n8.x4.shared.b16 {%0,%1,%2,%3}, [%4];"
                 : "=r"(r[0]), "=r"(r[1]), "=r"(r[2]), "=r"(r[3]) : "r"(addr));
}
__device__ __forceinline__ void ldsm_x4_t(uint32_t* r, uint32_t addr) {
    asm volatile("ldmatrix.sync.aligned.m8n8.x4.trans.shared.b16 {%0,%1,%2,%3}, [%4];"
                 : "=r"(r[0]), "=r"(r[1]), "=r"(r[2]), "=r"(r[3]) : "r"(addr));
}
__device__ __forceinline__ void mma_f16(float* d, const uint32_t* a, uint32_t b0, uint32_t b1) {
    asm volatile(
        "mma.sync.aligned.m16n8k16.row.col.f32.f16.f16.f32 "
        "{%0,%1,%2,%3}, {%4,%5,%6,%7}, {%8,%9}, {%0,%1,%2,%3};"
        : "+f"(d[0]), "+f"(d[1]), "+f"(d[2]), "+f"(d[3])
        : "r"(a[0]), "r"(a[1]), "r"(a[2]), "r"(a[3]), "r"(b0), "r"(b1));
}

// ---------------- kernel 0: reset expert counters ----------------
__global__ void zero_cnt_kernel() {
    if (threadIdx.x < NEXP) g_cnt[threadIdx.x] = 0;
}

// ---------------- prep: gate(+x cvt + out zero) | W1 straight cvt ----------------
__global__ void prep_kernel(const float* __restrict__ x,
                            const float* __restrict__ Wg,
                            const float* __restrict__ bg,
                            const float* __restrict__ W1,
                            float* __restrict__ out) {
    const int bid = blockIdx.x;
    const int tid = threadIdx.x;

    if (bid >= GATE_BLOCKS) {
        size_t base = (size_t)(bid - GATE_BLOCKS) * 16384 + (size_t)tid * 4;
#pragma unroll
        for (int j = 0; j < 16; j++) {
            size_t idx = base + (size_t)j * 1024;
            float4 v = *(const float4*)(W1 + idx);
            __half2 h0 = __floats2half2_rn(v.x, v.y);
            __half2 h1 = __floats2half2_rn(v.z, v.w);
            *(uint2*)(g_W1h + idx) = make_uint2(*(uint32_t*)&h0, *(uint32_t*)&h1);
        }
        return;
    }

    int warp = bid * 8 + (tid >> 5);
    int lane = tid & 31;

    const float4* xr4 = (const float4*)(x + (size_t)warp * DIM);
    __half2* xo = (__half2*)(g_xh + (size_t)warp * DIM);
    float4* oz = (float4*)(out + (size_t)warp * DIM);

    float acc[NEXP];
#pragma unroll
    for (int e = 0; e < NEXP; e++) acc[e] = 0.f;

#pragma unroll
    for (int it = 0; it < 8; it++) {
        int i4 = lane + it * 32;
        float4 xv = xr4[i4];
        xo[2 * i4]     = __floats2half2_rn(xv.x, xv.y);
        xo[2 * i4 + 1] = __floats2half2_rn(xv.z, xv.w);
        oz[i4] = make_float4(0.f, 0.f, 0.f, 0.f);
        const float* xs = (const float*)&xv;
#pragma unroll
        for (int c = 0; c < 4; c++) {
            float v = xs[c];
            const float4* w = reinterpret_cast<const float4*>(Wg + (size_t)(i4 * 4 + c) * NEXP);
            float4 w0 = w[0], w1 = w[1];
            acc[0] = fmaf(v, w0.x, acc[0]); acc[1] = fmaf(v, w0.y, acc[1]);
            acc[2] = fmaf(v, w0.z, acc[2]); acc[3] = fmaf(v, w0.w, acc[3]);
            acc[4] = fmaf(v, w1.x, acc[4]); acc[5] = fmaf(v, w1.y, acc[5]);
            acc[6] = fmaf(v, w1.z, acc[6]); acc[7] = fmaf(v, w1.w, acc[7]);
        }
    }
#pragma unroll
    for (int off = 16; off > 0; off >>= 1)
#pragma unroll
        for (int e = 0; e < NEXP; e++)
            acc[e] += __shfl_xor_sync(0xffffffffu, acc[e], off);

    if (lane == 0) {
        float lg[NEXP], mx = -1e30f;
#pragma unroll
        for (int e = 0; e < NEXP; e++) { lg[e] = acc[e] + bg[e]; mx = fmaxf(mx, lg[e]); }
        float p[NEXP], s = 0.f;
#pragma unroll
        for (int e = 0; e < NEXP; e++) { p[e] = expf(lg[e] - mx); s += p[e]; }
        float inv = 1.f / s;
        int i0 = 0;
#pragma unroll
        for (int e = 1; e < NEXP; e++) if (p[e] > p[i0]) i0 = e;
        int i1 = (i0 == 0) ? 1 : 0;
#pragma unroll
        for (int e = 0; e < NEXP; e++) if (e != i0 && p[e] > p[i1]) i1 = e;

        int pos0 = atomicAdd(&g_cnt[i0], 1);
        g_list[i0][pos0] = warp * 2 + 0;  g_gw[i0][pos0] = p[i0] * inv;
        int pos1 = atomicAdd(&g_cnt[i1], 1);
        g_list[i1][pos1] = warp * 2 + 1;  g_gw[i1][pos1] = p[i1] * inv;
    }
}

// ---------------- fp16 mma GEMM: 8 warps (64x32 tiles), 3-stage pipeline ----------------
// MODE 0: A = gathered g_xh, B = g_W1h, epi: half(relu(acc+b1)) -> g_h  (+W2 cvt CTAs)
// MODE 1: A = gathered g_h,  B = g_W2h, epi: atomicAdd(out, gw*(acc+b2))
template<int MODE, int KDIM, int NCOLS, int LOGN>
__global__ void __launch_bounds__(NT, 2)
moe_mma(const __half* __restrict__ Asrc, const __half* __restrict__ Wh,
        const float* __restrict__ bias, float* __restrict__ out,
        const float* __restrict__ cvt_src, __half* __restrict__ cvt_dst) {
    const int bid = blockIdx.x;
    const int tid = threadIdx.x;

    if (MODE == 0 && bid >= G1_BLOCKS) {
        size_t base = (size_t)(bid - G1_BLOCKS) * 16384 + (size_t)tid * 4;
#pragma unroll
        for (int j = 0; j < 16; j++) {
            size_t idx = base + (size_t)j * 1024;
            float4 v = *(const float4*)(cvt_src + idx);
            __half2 h0 = __floats2half2_rn(v.x, v.y);
            __half2 h1 = __floats2half2_rn(v.z, v.w);
            *(uint2*)(cvt_dst + idx) = make_uint2(*(uint32_t*)&h0, *(uint32_t*)&h1);
        }
        return;
    }

    const int e   = bid >> (5 + LOGN);
    const int cnt = g_cnt[e];
    const int m0  = (bid & 31) * BM;
    if (m0 >= cnt) return;
    const int gn0 = ((bid >> 5) & ((1 << LOGN) - 1)) * BN;

    extern __shared__ char smem[];
    int*   s_row = (int*)smem;                 // [128]
    float* s_gw  = (float*)(smem + 512);       // [128]

    const int wid  = tid >> 5, lane = tid & 31;
    const int wm   = (wid >> 2) * 64;          // 0,64
    const int wn   = (wid & 3) * 32;           // 0,32,64,96
    const int g    = lane >> 2;
    const int tg   = lane & 3;

    for (int i = tid; i < BM; i += NT) {
        int r = m0 + i;
        if (r < cnt) { s_row[i] = g_list[e][r]; s_gw[i] = g_gw[e][r]; }
        else         { s_row[i] = -1;           s_gw[i] = 0.f; }
    }
    __syncthreads();

    const uint32_t tiles_b = smem_u32(smem) + 1024;

    // A loader: 4 chunks of 16B; chunk i -> row lrow+32i, col c8
    const int lrow = tid >> 3, c8 = tid & 7;
    uint32_t a_off[4];
#pragma unroll
    for (int i = 0; i < 4; i++) {
        int p = s_row[lrow + i * 32];
        int arow = (p >= 0) ? (MODE == 0 ? (p >> 1) : p) : 0;
        a_off[i] = (uint32_t)arow * KDIM + c8 * 8;
    }
    const uint32_t a_dst0 = (uint32_t)(lrow * ROWA + c8 * 16);
    const uint32_t rstepA = 32 * ROWA;

    // B loader (K-major): 4 chunks; chunk i -> k-row brow+16i
    const int brow = tid >> 4, bc16 = tid & 15;
    const __half* b_base = Wh + ((size_t)e * KDIM + brow) * NCOLS + gn0 + bc16 * 8;
    const uint32_t b_dst0 = (uint32_t)(TILE_A + brow * ROWBB + bc16 * 16);
    const uint32_t bstep  = 16 * ROWBB;

    // LDSM lane addressing
    const uint32_t a_lane = (uint32_t)((lane & 15) * ROWA + (lane >> 4) * 16);
    const uint32_t bt_row = (uint32_t)(lane & 15);
    const uint32_t bt_col = (uint32_t)(((lane >> 4) & 1) * 16);

    float acc[4][4][4];
#pragma unroll
    for (int i = 0; i < 4; i++)
#pragma unroll
        for (int j = 0; j < 4; j++)
#pragma unroll
            for (int q = 0; q < 4; q++) acc[i][j][q] = 0.f;

    const int KT = KDIM / BKH;

    // prologue: stages 0 and 1
#pragma unroll
    for (int st = 0; st < 2; st++) {
        const uint32_t sb = tiles_b + st * STAGE_B;
        const int kk = st * BKH;
#pragma unroll
        for (int i = 0; i < 4; i++) {
            cp_async16(sb + a_dst0 + i * rstepA, Asrc + a_off[i] + kk);
            cp_async16(sb + b_dst0 + i * bstep,
                       b_base + (size_t)(kk + 16 * i) * NCOLS);
        }
        CP_COMMIT();
    }

    int stc = 0;   // compute stage, stp = prefetch stage rotates +2
    int stp = 2;
#pragma unroll 1
    for (int t = 0; t < KT; ++t) {
        if (t + 2 < KT) {
            const uint32_t sb = tiles_b + stp * STAGE_B;
            const int k2 = (t + 2) * BKH;
#pragma unroll
            for (int i = 0; i < 4; i++) {
                cp_async16(sb + a_dst0 + i * rstepA, Asrc + a_off[i] + k2);
                cp_async16(sb + b_dst0 + i * bstep,
                           b_base + (size_t)(k2 + 16 * i) * NCOLS);
            }
        }
        CP_COMMIT();
        CP_WAIT2();
        __syncthreads();

        const uint32_t As_b = tiles_b + stc * STAGE_B;
        const uint32_t Bs_b = As_b + TILE_A;
#pragma unroll
        for (int s = 0; s < 4; s++) {
            uint32_t af[4][4];
#pragma unroll
            for (int i = 0; i < 4; i++)
                ldsm_x4(af[i], As_b + (uint32_t)(wm + 16 * i) * ROWA + s * 32 + a_lane);
            uint32_t bf[2][4];
#pragma unroll
            for (int j2 = 0; j2 < 2; j2++)
                ldsm_x4_t(bf[j2], Bs_b + (uint32_t)(s * 16 + bt_row) * ROWBB
                                   + (uint32_t)(wn * 2 + j2 * 32) + bt_col);
#pragma unroll
            for (int i = 0; i < 4; i++)
#pragma unroll
                for (int j2 = 0; j2 < 2; j2++) {
                    mma_f16(acc[i][2 * j2],     af[i], bf[j2][0], bf[j2][1]);
                    mma_f16(acc[i][2 * j2 + 1], af[i], bf[j2][2], bf[j2][3]);
                }
        }
        __syncthreads();
        stc = (stc == NSTAGE - 1) ? 0 : stc + 1;
        stp = (stp == NSTAGE - 1) ? 0 : stp + 1;
    }

    // ---------------- epilogue ----------------
#pragma unroll
    for (int i = 0; i < 4; i++) {
        const int rl = wm + i * 16 + g;
        const int pl = s_row[rl],  ph = s_row[rl + 8];
        const float gl = s_gw[rl], gh2 = s_gw[rl + 8];
#pragma unroll
        for (int j = 0; j < 4; j++) {
            const int n = gn0 + wn + j * 8 + 2 * tg;
            const float2 bb = *(const float2*)(bias + (size_t)e * NCOLS + n);
            if (MODE == 0) {
                if (pl >= 0)
                    *(__half2*)(g_h + (size_t)pl * HIDDEN + n) =
                        __floats2half2_rn(fmaxf(acc[i][j][0] + bb.x, 0.f),
                                          fmaxf(acc[i][j][1] + bb.y, 0.f));
                if (ph >= 0)
                    *(__half2*)(g_h + (size_t)ph * HIDDEN + n) =
                        __floats2half2_rn(fmaxf(acc[i][j][2] + bb.x, 0.f),
                                          fmaxf(acc[i][j][3] + bb.y, 0.f));
            } else {
                // two commutative addends onto 0.0f per element -> deterministic
                if (pl >= 0) {
                    float* op = out + (size_t)(pl >> 1) * DIM + n;
                    atomicAdd(op,     gl * (acc[i][j][0] + bb.x));
                    atomicAdd(op + 1, gl * (acc[i][j][1] + bb.y));
                }
                if (ph >= 0) {
                    float* op = out + (size_t)(ph >> 1) * DIM + n;
                    atomicAdd(op,     gh2 * (acc[i][j][2] + bb.x));
                    atomicAdd(op + 1, gh2 * (acc[i][j][3] + bb.y));
                }
            }
        }
    }
}

// ---------------- launch ----------------
static constexpr int SMEM_BYTES = 1024 + NSTAGE * STAGE_B;   // 108544

extern "C" void kernel_launch(void* const* d_in, const int* in_sizes, int n_in,
                              void* d_out, int out_size) {
    const float* x  = (const float*)d_in[0];
    const float* Wg = (const float*)d_in[1];
    const float* bg = (const float*)d_in[2];
    const float* W1 = (const float*)d_in[3];
    const float* b1 = (const float*)d_in[4];
    const float* W2 = (const float*)d_in[5];
    const float* b2 = (const float*)d_in[6];
    float* out = (float*)d_out;

    cudaFuncSetAttribute(moe_mma<0, DIM, HIDDEN, 5>,
                         cudaFuncAttributeMaxDynamicSharedMemorySize, SMEM_BYTES);
    cudaFuncSetAttribute(moe_mma<1, HIDDEN, DIM, 3>,
                         cudaFuncAttributeMaxDynamicSharedMemorySize, SMEM_BYTES);

    __half* W1h; cudaGetSymbolAddress((void**)&W1h, g_W1h);
    __half* W2h; cudaGetSymbolAddress((void**)&W2h, g_W2h);
    __half* xh;  cudaGetSymbolAddress((void**)&xh,  g_xh);
    __half* gh;  cudaGetSymbolAddress((void**)&gh,  g_h);

    zero_cnt_kernel<<<1, 32>>>();
    prep_kernel<<<GATE_BLOCKS + W1CVT_BLOCKS, 256>>>(x, Wg, bg, W1, out);
    moe_mma<0, DIM, HIDDEN, 5><<<G1_BLOCKS + W2CVT_BLOCKS, NT, SMEM_BYTES>>>(
        xh, W1h, b1, nullptr, W2, W2h);
    moe_mma<1, HIDDEN, DIM, 3><<<32 * 8 * NEXP, NT, SMEM_BYTES>>>(
        gh, W2h, b2, out, nullptr, nullptr);
}

// round 13
// speedup vs baseline: 1.2465x; 1.0104x over previous
#include <cuda_runtime.h>
#include <cuda_fp16.h>
#include <math.h>
#include <stdint.h>

#define NTOK   4096
#define DIM    1024
#define NEXP   8
#define HIDDEN 4096

#define BM 128
#define BN 128
#define BKH 64            // K halfs per k-tile
#define NT 256
#define ROWA 144          // A SMEM row stride bytes
#define ROWBB 272         // B SMEM row stride bytes

#define TILE_A  (BM * ROWA)          // 18432
#define TILE_BB (BKH * ROWBB)        // 17408
#define STAGE_B (TILE_A + TILE_BB)   // 35840
#define NSTAGE  3

#define GATE_BLOCKS 512
#define W1CVT_BLOCKS 2048
#define G1_BLOCKS  8192              // 32m * 32n * 8e
#define CVT_CHUNKS 8192u             // W2 cvt: 8192 chunks x 1024 float4

// ---------------- scratch (__device__ statics — alloc-free) ----------------
__device__ int    g_cnt[NEXP];
__device__ unsigned int g_cvt;
__device__ int    g_list[NEXP][NTOK];
__device__ float  g_gw[NEXP][NTOK];
__device__ __half g_xh[(size_t)NTOK * DIM];
__device__ __half g_h[(size_t)NTOK * 2 * HIDDEN];
__device__ __half g_W1h[(size_t)NEXP * DIM * HIDDEN];     // [e][k][n] fp16
__device__ __half g_W2h[(size_t)NEXP * HIDDEN * DIM];     // [e][k][n] fp16

// ---------------- helpers ----------------
__device__ __forceinline__ uint32_t smem_u32(const void* p) {
    uint32_t a;
    asm("{ .reg .u64 t; cvta.to.shared.u64 t, %1; cvt.u32.u64 %0, t; }" : "=r"(a) : "l"(p));
    return a;
}
__device__ __forceinline__ void cp_async16(uint32_t dst, const void* src) {
    asm volatile("cp.async.cg.shared.global [%0], [%1], 16;" :: "r"(dst), "l"(src));
}
#define CP_COMMIT() asm volatile("cp.async.commit_group;" ::: "memory")
#define CP_WAIT2()  asm volatile("cp.async.wait_group 2;" ::: "memory")

__device__ __forceinline__ void ldsm_x4(uint32_t* r, uint32_t addr) {
    asm volatile("ldmatrix.sync.aligned.m8n8.x4.shared.b16 {%0,%1,%2,%3}, [%4];"
                 : "=r"(r[0]), "=r"(r[1]), "=r"(r[2]), "=r"(r[3]) : "r"(addr));
}
__device__ __forceinline__ void ldsm_x4_t(uint32_t* r, uint32_t addr) {
    asm volatile("ldmatrix.sync.aligned.m8n8.x4.trans.shared.b16 {%0,%1,%2,%3}, [%4];"
                 : "=r"(r[0]), "=r"(r[1]), "=r"(r[2]), "=r"(r[3]) : "r"(addr));
}
__device__ __forceinline__ void mma_f16(float* d, const uint32_t* a, uint32_t b0, uint32_t b1) {
    asm volatile(
        "mma.sync.aligned.m16n8k16.row.col.f32.f16.f16.f32 "
        "{%0,%1,%2,%3}, {%4,%5,%6,%7}, {%8,%9}, {%0,%1,%2,%3};"
        : "+f"(d[0]), "+f"(d[1]), "+f"(d[2]), "+f"(d[3])
        : "r"(a[0]), "r"(a[1]), "r"(a[2]), "r"(a[3]), "r"(b0), "r"(b1));
}

// ---------------- kernel 0: reset counters ----------------
__global__ void zero_cnt_kernel() {
    if (threadIdx.x < NEXP) g_cnt[threadIdx.x] = 0;
    if (threadIdx.x == 0)   g_cvt = 0u;
}

// ---------------- prep: gate(+x cvt + out zero) | W1 straight cvt ----------------
__global__ void prep_kernel(const float* __restrict__ x,
                            const float* __restrict__ Wg,
                            const float* __restrict__ bg,
                            const float* __restrict__ W1,
                            float* __restrict__ out) {
    const int bid = blockIdx.x;
    const int tid = threadIdx.x;

    if (bid >= GATE_BLOCKS) {
        size_t base = (size_t)(bid - GATE_BLOCKS) * 16384 + (size_t)tid * 4;
#pragma unroll
        for (int j = 0; j < 16; j++) {
            size_t idx = base + (size_t)j * 1024;
            float4 v = *(const float4*)(W1 + idx);
            __half2 h0 = __floats2half2_rn(v.x, v.y);
            __half2 h1 = __floats2half2_rn(v.z, v.w);
            *(uint2*)(g_W1h + idx) = make_uint2(*(uint32_t*)&h0, *(uint32_t*)&h1);
        }
        return;
    }

    int warp = bid * 8 + (tid >> 5);
    int lane = tid & 31;

    const float4* xr4 = (const float4*)(x + (size_t)warp * DIM);
    __half2* xo = (__half2*)(g_xh + (size_t)warp * DIM);
    float4* oz = (float4*)(out + (size_t)warp * DIM);

    float acc[NEXP];
#pragma unroll
    for (int e = 0; e < NEXP; e++) acc[e] = 0.f;

#pragma unroll
    for (int it = 0; it < 8; it++) {
        int i4 = lane + it * 32;
        float4 xv = xr4[i4];
        xo[2 * i4]     = __floats2half2_rn(xv.x, xv.y);
        xo[2 * i4 + 1] = __floats2half2_rn(xv.z, xv.w);
        oz[i4] = make_float4(0.f, 0.f, 0.f, 0.f);
        const float* xs = (const float*)&xv;
#pragma unroll
        for (int c = 0; c < 4; c++) {
            float v = xs[c];
            const float4* w = reinterpret_cast<const float4*>(Wg + (size_t)(i4 * 4 + c) * NEXP);
            float4 w0 = w[0], w1 = w[1];
            acc[0] = fmaf(v, w0.x, acc[0]); acc[1] = fmaf(v, w0.y, acc[1]);
            acc[2] = fmaf(v, w0.z, acc[2]); acc[3] = fmaf(v, w0.w, acc[3]);
            acc[4] = fmaf(v, w1.x, acc[4]); acc[5] = fmaf(v, w1.y, acc[5]);
            acc[6] = fmaf(v, w1.z, acc[6]); acc[7] = fmaf(v, w1.w, acc[7]);
        }
    }
#pragma unroll
    for (int off = 16; off > 0; off >>= 1)
#pragma unroll
        for (int e = 0; e < NEXP; e++)
            acc[e] += __shfl_xor_sync(0xffffffffu, acc[e], off);

    if (lane == 0) {
        float lg[NEXP], mx = -1e30f;
#pragma unroll
        for (int e = 0; e < NEXP; e++) { lg[e] = acc[e] + bg[e]; mx = fmaxf(mx, lg[e]); }
        float p[NEXP], s = 0.f;
#pragma unroll
        for (int e = 0; e < NEXP; e++) { p[e] = expf(lg[e] - mx); s += p[e]; }
        float inv = 1.f / s;
        int i0 = 0;
#pragma unroll
        for (int e = 1; e < NEXP; e++) if (p[e] > p[i0]) i0 = e;
        int i1 = (i0 == 0) ? 1 : 0;
#pragma unroll
        for (int e = 0; e < NEXP; e++) if (e != i0 && p[e] > p[i1]) i1 = e;

        int pos0 = atomicAdd(&g_cnt[i0], 1);
        g_list[i0][pos0] = warp * 2 + 0;  g_gw[i0][pos0] = p[i0] * inv;
        int pos1 = atomicAdd(&g_cnt[i1], 1);
        g_list[i1][pos1] = warp * 2 + 1;  g_gw[i1][pos1] = p[i1] * inv;
    }
}

// ---------------- fp16 mma GEMM: 8 warps (64x32 tiles), 3-stage pipeline ----------------
// MODE 0: A = gathered g_xh, B = g_W1h, epi: half(relu(acc+b1)) -> g_h
//         W2 fp32->fp16 cvt stuffed into the mainloop's idle issue slots
//         (chunks claimed via g_cvt; active CTAs >= 2048, 4 chunks each covers all 8192).
// MODE 1: A = gathered g_h,  B = g_W2h, epi: atomicAdd(out, gw*(acc+b2))
template<int MODE, int KDIM, int NCOLS, int LOGN>
__global__ void __launch_bounds__(NT, 2)
moe_mma(const __half* __restrict__ Asrc, const __half* __restrict__ Wh,
        const float* __restrict__ bias, float* __restrict__ out,
        const float* __restrict__ cvt_src, __half* __restrict__ cvt_dst) {
    const int bid = blockIdx.x;
    const int tid = threadIdx.x;

    const int e   = bid >> (5 + LOGN);
    const int cnt = g_cnt[e];
    const int m0  = (bid & 31) * BM;
    if (m0 >= cnt) return;
    const int gn0 = ((bid >> 5) & ((1 << LOGN) - 1)) * BN;

    extern __shared__ char smem[];
    int*      s_row = (int*)smem;                 // [128] @ 0
    float*    s_gw  = (float*)(smem + 512);       // [128] @ 512
    unsigned* s_cvt = (unsigned*)(smem + 1024);   // @ 1024

    const int wid  = tid >> 5, lane = tid & 31;
    const int wm   = (wid >> 2) * 64;          // 0,64
    const int wn   = (wid & 3) * 32;           // 0,32,64,96
    const int g    = lane >> 2;
    const int tg   = lane & 3;

    for (int i = tid; i < BM; i += NT) {
        int r = m0 + i;
        if (r < cnt) { s_row[i] = g_list[e][r]; s_gw[i] = g_gw[e][r]; }
        else         { s_row[i] = -1;           s_gw[i] = 0.f; }
    }
    if (MODE == 0 && tid == 0) *s_cvt = atomicAdd(&g_cvt, 4u);
    __syncthreads();
    const unsigned cvt_base = (MODE == 0) ? *s_cvt : 0u;

    const uint32_t tiles_b = smem_u32(smem) + 1280;

    // A loader: 4 chunks of 16B; chunk i -> row lrow+32i, col c8
    const int lrow = tid >> 3, c8 = tid & 7;
    uint32_t a_off[4];
#pragma unroll
    for (int i = 0; i < 4; i++) {
        int p = s_row[lrow + i * 32];
        int arow = (p >= 0) ? (MODE == 0 ? (p >> 1) : p) : 0;
        a_off[i] = (uint32_t)arow * KDIM + c8 * 8;
    }
    const uint32_t a_dst0 = (uint32_t)(lrow * ROWA + c8 * 16);
    const uint32_t rstepA = 32 * ROWA;

    // B loader (K-major): 4 chunks; chunk i -> k-row brow+16i
    const int brow = tid >> 4, bc16 = tid & 15;
    const __half* b_base = Wh + ((size_t)e * KDIM + brow) * NCOLS + gn0 + bc16 * 8;
    const uint32_t b_dst0 = (uint32_t)(TILE_A + brow * ROWBB + bc16 * 16);
    const uint32_t bstep  = 16 * ROWBB;

    // LDSM lane addressing
    const uint32_t a_lane = (uint32_t)((lane & 15) * ROWA + (lane >> 4) * 16);
    const uint32_t bt_row = (uint32_t)(lane & 15);
    const uint32_t bt_col = (uint32_t)(((lane >> 4) & 1) * 16);

    float acc[4][4][4];
#pragma unroll
    for (int i = 0; i < 4; i++)
#pragma unroll
        for (int j = 0; j < 4; j++)
#pragma unroll
            for (int q = 0; q < 4; q++) acc[i][j][q] = 0.f;

    const int KT = KDIM / BKH;

    // prologue: stages 0 and 1
#pragma unroll
    for (int st = 0; st < 2; st++) {
        const uint32_t sb = tiles_b + st * STAGE_B;
        const int kk = st * BKH;
#pragma unroll
        for (int i = 0; i < 4; i++) {
            cp_async16(sb + a_dst0 + i * rstepA, Asrc + a_off[i] + kk);
            cp_async16(sb + b_dst0 + i * bstep,
                       b_base + (size_t)(kk + 16 * i) * NCOLS);
        }
        CP_COMMIT();
    }

    int stc = 0;
    int stp = 2;
#pragma unroll 1
    for (int t = 0; t < KT; ++t) {
        // ---- stuffed W2 cvt: load early (latency hides under the k-iter) ----
        float4 vv;
        bool do_cvt = false;
        size_t fidx = 0;
        if (MODE == 0) {
            unsigned ck = cvt_base + (unsigned)(t >> 2);
            if (ck < CVT_CHUNKS) {
                fidx = (size_t)ck * 1024 + (size_t)(t & 3) * 256 + tid;
                vv = ((const float4*)cvt_src)[fidx];
                do_cvt = true;
            }
        }

        if (t + 2 < KT) {
            const uint32_t sb = tiles_b + stp * STAGE_B;
            const int k2 = (t + 2) * BKH;
#pragma unroll
            for (int i = 0; i < 4; i++) {
                cp_async16(sb + a_dst0 + i * rstepA, Asrc + a_off[i] + k2);
                cp_async16(sb + b_dst0 + i * bstep,
                           b_base + (size_t)(k2 + 16 * i) * NCOLS);
            }
        }
        CP_COMMIT();
        CP_WAIT2();
        __syncthreads();

        const uint32_t As_b = tiles_b + stc * STAGE_B;
        const uint32_t Bs_b = As_b + TILE_A;
#pragma unroll
        for (int s = 0; s < 4; s++) {
            uint32_t af[4][4];
#pragma unroll
            for (int i = 0; i < 4; i++)
                ldsm_x4(af[i], As_b + (uint32_t)(wm + 16 * i) * ROWA + s * 32 + a_lane);
            uint32_t bf[2][4];
#pragma unroll
            for (int j2 = 0; j2 < 2; j2++)
                ldsm_x4_t(bf[j2], Bs_b + (uint32_t)(s * 16 + bt_row) * ROWBB
                                   + (uint32_t)(wn * 2 + j2 * 32) + bt_col);
#pragma unroll
            for (int i = 0; i < 4; i++)
#pragma unroll
                for (int j2 = 0; j2 < 2; j2++) {
                    mma_f16(acc[i][2 * j2],     af[i], bf[j2][0], bf[j2][1]);
                    mma_f16(acc[i][2 * j2 + 1], af[i], bf[j2][2], bf[j2][3]);
                }
        }

        // ---- stuffed W2 cvt: convert + store after compute ----
        if (MODE == 0 && do_cvt) {
            __half2 h0 = __floats2half2_rn(vv.x, vv.y);
            __half2 h1 = __floats2half2_rn(vv.z, vv.w);
            ((uint2*)cvt_dst)[fidx] = make_uint2(*(uint32_t*)&h0, *(uint32_t*)&h1);
        }

        __syncthreads();
        stc = (stc == NSTAGE - 1) ? 0 : stc + 1;
        stp = (stp == NSTAGE - 1) ? 0 : stp + 1;
    }

    // ---------------- epilogue ----------------
#pragma unroll
    for (int i = 0; i < 4; i++) {
        const int rl = wm + i * 16 + g;
        const int pl = s_row[rl],  ph = s_row[rl + 8];
        const float gl = s_gw[rl], gh2 = s_gw[rl + 8];
#pragma unroll
        for (int j = 0; j < 4; j++) {
            const int n = gn0 + wn + j * 8 + 2 * tg;
            const float2 bb = *(const float2*)(bias + (size_t)e * NCOLS + n);
            if (MODE == 0) {
                if (pl >= 0)
                    *(__half2*)(g_h + (size_t)pl * HIDDEN + n) =
                        __floats2half2_rn(fmaxf(acc[i][j][0] + bb.x, 0.f),
                                          fmaxf(acc[i][j][1] + bb.y, 0.f));
                if (ph >= 0)
                    *(__half2*)(g_h + (size_t)ph * HIDDEN + n) =
                        __floats2half2_rn(fmaxf(acc[i][j][2] + bb.x, 0.f),
                                          fmaxf(acc[i][j][3] + bb.y, 0.f));
            } else {
                // two commutative addends onto 0.0f per element -> deterministic
                if (pl >= 0) {
                    float* op = out + (size_t)(pl >> 1) * DIM + n;
                    atomicAdd(op,     gl * (acc[i][j][0] + bb.x));
                    atomicAdd(op + 1, gl * (acc[i][j][1] + bb.y));
                }
                if (ph >= 0) {
                    float* op = out + (size_t)(ph >> 1) * DIM + n;
                    atomicAdd(op,     gh2 * (acc[i][j][2] + bb.x));
                    atomicAdd(op + 1, gh2 * (acc[i][j][3] + bb.y));
                }
            }
        }
    }
}

// ---------------- launch ----------------
static constexpr int SMEM_BYTES = 1280 + NSTAGE * STAGE_B;   // 108800

extern "C" void kernel_launch(void* const* d_in, const int* in_sizes, int n_in,
                              void* d_out, int out_size) {
    const float* x  = (const float*)d_in[0];
    const float* Wg = (const float*)d_in[1];
    const float* bg = (const float*)d_in[2];
    const float* W1 = (const float*)d_in[3];
    const float* b1 = (const float*)d_in[4];
    const float* W2 = (const float*)d_in[5];
    const float* b2 = (const float*)d_in[6];
    float* out = (float*)d_out;

    cudaFuncSetAttribute(moe_mma<0, DIM, HIDDEN, 5>,
                         cudaFuncAttributeMaxDynamicSharedMemorySize, SMEM_BYTES);
    cudaFuncSetAttribute(moe_mma<1, HIDDEN, DIM, 3>,
                         cudaFuncAttributeMaxDynamicSharedMemorySize, SMEM_BYTES);

    __half* W1h; cudaGetSymbolAddress((void**)&W1h, g_W1h);
    __half* W2h; cudaGetSymbolAddress((void**)&W2h, g_W2h);
    __half* xh;  cudaGetSymbolAddress((void**)&xh,  g_xh);
    __half* gh;  cudaGetSymbolAddress((void**)&gh,  g_h);

    zero_cnt_kernel<<<1, 32>>>();
    prep_kernel<<<GATE_BLOCKS + W1CVT_BLOCKS, 256>>>(x, Wg, bg, W1, out);
    moe_mma<0, DIM, HIDDEN, 5><<<G1_BLOCKS, NT, SMEM_BYTES>>>(
        xh, W1h, b1, nullptr, W2, W2h);
    moe_mma<1, HIDDEN, DIM, 3><<<32 * 8 * NEXP, NT, SMEM_BYTES>>>(
        gh, W2h, b2, out, nullptr, nullptr);
}